// round 14
// baseline (speedup 1.0000x reference)
#include <cuda_runtime.h>
#include <cuda_fp16.h>
#include <cstdint>

// Problem constants
#define NB    16
#define CDIM  2048
#define RF    256
#define HW    128
#define PN    64
#define TOPK  10
#define KF    (CDIM*HW)
#define COMPC (1.0f - 1.0f/262144.0f)   // calibration collapses: pos=0.5, comp=1-2^-18

// ---------------- device scratch (no allocations allowed) ----------------
__device__ float  g_dot[NB*PN];
__device__ float  g_pn [PN];
__device__ int    g_idx[NB*TOPK];
__device__ __half g_wrf_h[RF*CDIM];
__device__ __half g_wmv_h[CDIM*TOPK*RF];
__device__ __half g_wrm_h[CDIM*CDIM];
__device__ __half g_wfu_h[CDIM*CDIM];
__device__ __half g_xp_h [(size_t)PN*RF*HW];      // [p][rf][hw]
__device__ __half g_mvl_h[(size_t)NB*CDIM*HW];    // [b][c][hw]
__device__ __half g_mva_h[(size_t)NB*CDIM*HW];    // [b][c][hw]

// ---------------- helpers ----------------
__device__ __forceinline__ uint32_t s2u(const void* p) {
    return (uint32_t)__cvta_generic_to_shared(p);
}
__device__ __forceinline__ void cp16(uint32_t dst, const void* src) {
    asm volatile("cp.async.cg.shared.global [%0], [%1], 16;" :: "r"(dst), "l"(src));
}
__device__ __forceinline__ void ldsm_x4(uint32_t* r, uint32_t addr) {
    asm volatile("ldmatrix.sync.aligned.m8n8.x4.shared.b16 {%0,%1,%2,%3}, [%4];"
                 : "=r"(r[0]), "=r"(r[1]), "=r"(r[2]), "=r"(r[3]) : "r"(addr));
}
__device__ __forceinline__ void ldsm_x4t(uint32_t* r, uint32_t addr) {
    asm volatile("ldmatrix.sync.aligned.m8n8.x4.trans.shared.b16 {%0,%1,%2,%3}, [%4];"
                 : "=r"(r[0]), "=r"(r[1]), "=r"(r[2]), "=r"(r[3]) : "r"(addr));
}
__device__ __forceinline__ void mma16816(float* c, const uint32_t* a, const uint32_t* b) {
    asm volatile(
        "mma.sync.aligned.m16n8k16.row.col.f32.f16.f16.f32 "
        "{%0,%1,%2,%3}, {%4,%5,%6,%7}, {%8,%9}, {%0,%1,%2,%3};"
        : "+f"(c[0]), "+f"(c[1]), "+f"(c[2]), "+f"(c[3])
        : "r"(a[0]), "r"(a[1]), "r"(a[2]), "r"(a[3]), "r"(b[0]), "r"(b[1]));
}

// ---------------- stage 1: pairwise dots + ||p||^2 (fp32, exact topk) -------
__global__ __launch_bounds__(256) void dist_kernel(
    const float* __restrict__ x, const float* __restrict__ p)
{
    __shared__ float sx[NB][128];
    __shared__ float sp[PN][129];
    const int t = threadIdx.x;
    const size_t k0 = (size_t)blockIdx.x * 128;
    #pragma unroll
    for (int l = 0; l < 2; l++) {
        int f = t + l * 256;
        int n = f >> 5, c4 = f & 31;
        float4 v = *(const float4*)(x + (size_t)n * KF + k0 + c4 * 4);
        sx[n][c4*4+0] = v.x; sx[n][c4*4+1] = v.y;
        sx[n][c4*4+2] = v.z; sx[n][c4*4+3] = v.w;
    }
    #pragma unroll
    for (int l = 0; l < 8; l++) {
        int f = t + l * 256;
        int q = f >> 5, c4 = f & 31;
        float4 v = *(const float4*)(p + (size_t)q * KF + k0 + c4 * 4);
        sp[q][c4*4+0] = v.x; sp[q][c4*4+1] = v.y;
        sp[q][c4*4+2] = v.z; sp[q][c4*4+3] = v.w;
    }
    __syncthreads();
    const int n = t >> 4, pg = (t & 15) * 4;
    float a0 = 0.f, a1 = 0.f, a2 = 0.f, a3 = 0.f;
    #pragma unroll 8
    for (int k = 0; k < 128; k++) {
        float xv = sx[n][k];
        a0 = fmaf(xv, sp[pg+0][k], a0);
        a1 = fmaf(xv, sp[pg+1][k], a1);
        a2 = fmaf(xv, sp[pg+2][k], a2);
        a3 = fmaf(xv, sp[pg+3][k], a3);
    }
    atomicAdd(&g_dot[n*PN + pg+0], a0);
    atomicAdd(&g_dot[n*PN + pg+1], a1);
    atomicAdd(&g_dot[n*PN + pg+2], a2);
    atomicAdd(&g_dot[n*PN + pg+3], a3);
    if (t < PN) {
        float s = 0.f;
        #pragma unroll 8
        for (int k = 0; k < 128; k++) { float v = sp[t][k]; s = fmaf(v, v, s); }
        atomicAdd(&g_pn[t], s);
    }
}

// ---------------- stage 2: top-10 ----------------
__global__ void topk_kernel() {
    int n = threadIdx.x;
    if (n >= NB) return;
    float d[PN]; bool used[PN];
    for (int q = 0; q < PN; q++) {
        d[q] = g_pn[q] - 2.0f * g_dot[n*PN + q];
        used[q] = false;
    }
    for (int j = 0; j < TOPK; j++) {
        float best = 3.402823e38f; int bi = 0;
        for (int q = 0; q < PN; q++)
            if (!used[q] && d[q] < best) { best = d[q]; bi = q; }
        used[bi] = true;
        g_idx[n*TOPK + j] = bi;
    }
}

// ---------------- fp32 -> fp16 converts ----------------
__global__ void f2h_kernel(const float* __restrict__ in, __half* __restrict__ out, int n4) {
    int i = blockIdx.x * blockDim.x + threadIdx.x;
    if (i >= n4) return;
    float4 v = ((const float4*)in)[i];
    ((__half2*)out)[2*i]   = __floats2half2_rn(v.x, v.y);
    ((__half2*)out)[2*i+1] = __floats2half2_rn(v.z, v.w);
}
__global__ void f2h3_kernel(const float* __restrict__ a, __half* __restrict__ ah, int na4,
                            const float* __restrict__ b, __half* __restrict__ bh, int nb4,
                            const float* __restrict__ c, __half* __restrict__ ch, int nc4)
{
    int j = blockIdx.x * blockDim.x + threadIdx.x;
    const float* src; __half* dst;
    if (j < na4) { src = a; dst = ah; }
    else if ((j -= na4) < nb4) { src = b; dst = bh; }
    else if ((j -= nb4) < nc4) { src = c; dst = ch; }
    else return;
    float4 v = ((const float4*)src)[j];
    ((__half2*)dst)[2*j]   = __floats2half2_rn(v.x, v.y);
    ((__half2*)dst)[2*j+1] = __floats2half2_rn(v.z, v.w);
}

// ---------------- gemm0: 64x128 tile, fp32 B via SMEM staging + convert -----
// g_xp_h[p] = w_rf @ proto_fp32[p], K=2048. A fp16 (cp.async), B fp32 staged
// via cp.async then converted (__floats2half2_rn -> bit-identical to the old
// f2h pass) into the standard swizzled fp16 tile. Runs concurrent with dist.
#define G0_STAGE (8192 + 16384 + 32768)   // A + fp16 tile + fp32 staging
#define G0_SMEM  (2*G0_STAGE)             // 114688

__global__ __launch_bounds__(256, 2) void gemm0_f32b(
    const __half* __restrict__ A, const float* __restrict__ Bf)
{
    extern __shared__ char smem[];
    const uint32_t sbase = s2u(smem);
    const int tid  = threadIdx.x;
    const int lane = tid & 31;
    const int wid  = tid >> 5;
    const int wm   = wid >> 2;       // 0..1 (32 rows each)
    const int wn   = wid & 3;        // 0..3 (32 cols each)
    const int row0 = blockIdx.x * 64;
    const int bb   = blockIdx.y;
    const float* Bb = Bf + (size_t)bb * CDIM * HW;

    float acc[2][4][4];
    #pragma unroll
    for (int mi = 0; mi < 2; mi++)
        #pragma unroll
        for (int ni = 0; ni < 4; ni++)
            #pragma unroll
            for (int e = 0; e < 4; e++) acc[mi][ni][e] = 0.f;

    const int nk = CDIM >> 6;   // 32

    auto load_chunk = [&](int i) {
        const uint32_t base = sbase + (i & 1) * G0_STAGE;
        const int kt = i * 64;
        // A tile: 64 rows x 64 halves
        #pragma unroll
        for (int l = 0; l < 2; l++) {
            int c = tid + l * 256;
            int r = c >> 3, s = c & 7;
            cp16(base + r * 128 + (((s ^ (r & 7))) << 4),
                 A + (size_t)(row0 + r) * CDIM + kt + s * 8);
        }
        // B fp32 staging: 64 k-rows x 128 floats (512B rows, linear)
        #pragma unroll
        for (int l = 0; l < 8; l++) {
            int c = tid + l * 256;
            int k = c >> 5, f4 = c & 31;
            cp16(base + 24576 + k * 512 + f4 * 16,
                 Bb + (size_t)(kt + k) * HW + f4 * 4);
        }
        asm volatile("cp.async.commit_group;" ::: "memory");
    };

    load_chunk(0);
    for (int i = 0; i < nk; i++) {
        if (i + 1 < nk) {
            load_chunk(i + 1);
            asm volatile("cp.async.wait_group 1;" ::: "memory");
        } else {
            asm volatile("cp.async.wait_group 0;" ::: "memory");
        }
        __syncthreads();
        const char* stg = smem + (i & 1) * G0_STAGE + 24576;
        char*       til = smem + (i & 1) * G0_STAGE + 8192;
        // convert fp32 staging -> swizzled fp16 tile (1024 chunks / 256 thr)
        #pragma unroll
        for (int l = 0; l < 4; l++) {
            int c = tid + l * 256;
            int k = c >> 4, cn = c & 15;
            const float4* src = (const float4*)(stg + k * 512 + cn * 32);
            float4 v0 = src[0], v1 = src[1];
            __half2 h[4];
            h[0] = __floats2half2_rn(v0.x, v0.y);
            h[1] = __floats2half2_rn(v0.z, v0.w);
            h[2] = __floats2half2_rn(v1.x, v1.y);
            h[3] = __floats2half2_rn(v1.z, v1.w);
            *(uint4*)(til + k * 256 + ((cn & 8) << 4)
                          + (((cn & 7) ^ (k & 7)) << 4)) = *(uint4*)h;
        }
        __syncthreads();

        const uint32_t abase = sbase + (i & 1) * G0_STAGE;
        const uint32_t bbase = abase + 8192;
        #pragma unroll
        for (int ks = 0; ks < 4; ks++) {
            const int k0 = ks * 16;
            uint32_t af[2][4], bf[4][2];
            const int arow = wm * 32 + (lane & 15);
            const int sch  = (k0 >> 3) + (lane >> 4);
            #pragma unroll
            for (int mi = 0; mi < 2; mi++) {
                int r = arow + mi * 16;
                ldsm_x4(af[mi], abase + r * 128 + (((sch ^ (r & 7)) & 7) << 4));
            }
            const int krow = k0 + (lane & 15);
            #pragma unroll
            for (int pr = 0; pr < 2; pr++) {
                int cn = wn * 4 + pr * 2 + (lane >> 4);
                uint32_t t[4];
                ldsm_x4t(t, bbase + krow * 256 + ((cn & 8) << 4)
                              + (((cn & 7) ^ (krow & 7)) << 4));
                bf[pr*2+0][0] = t[0]; bf[pr*2+0][1] = t[1];
                bf[pr*2+1][0] = t[2]; bf[pr*2+1][1] = t[3];
            }
            #pragma unroll
            for (int mi = 0; mi < 2; mi++)
                #pragma unroll
                for (int ni = 0; ni < 4; ni++)
                    mma16816(acc[mi][ni], af[mi], bf[ni]);
        }
        __syncthreads();
    }

    const int quad = lane >> 2, qi = lane & 3;
    __half* dst = g_xp_h + (size_t)bb * RF * HW;
    #pragma unroll
    for (int mi = 0; mi < 2; mi++)
        #pragma unroll
        for (int rh = 0; rh < 2; rh++) {
            int m = row0 + wm * 32 + mi * 16 + quad + rh * 8;
            #pragma unroll
            for (int ni = 0; ni < 4; ni++) {
                int n = wn * 32 + ni * 8 + qi * 2;
                *(__half2*)(dst + (size_t)m * HW + n) =
                    __floats2half2_rn(acc[mi][ni][rh*2], acc[mi][ni][rh*2+1]);
            }
        }
}

// ---------------- chain HMMA GEMM: 128x128 tile (champion, unchanged) -------
// MODE 1: g_mvl_h[b] = relu(0.5X + COMPC*(wmv@gather))  K=2560
// MODE 2: g_mva_h[b] = instnorm(w_rm_s @ mvl)           K=2048
// MODE 3: out[b]     = X * (1 + sigmoid(w_fuse @ mva))  K=2048
#define BUFB 32768
#define SMEM128 (2*BUFB)

template<int MODE>
__global__ __launch_bounds__(256, 2) void gemm_hmma(
    const __half* __restrict__ A,
    const float* __restrict__ X, float* __restrict__ Out, int K, int bb0)
{
    extern __shared__ char smem[];
    const uint32_t sbase = s2u(smem);
    const int tid  = threadIdx.x;
    const int lane = tid & 31;
    const int wid  = tid >> 5;
    const int wm   = wid >> 2;
    const int wn   = wid & 3;
    const int row0 = blockIdx.x * 128;
    const int bb   = blockIdx.y + bb0;

    const __half* Bb = nullptr;
    if (MODE == 2) Bb = g_mvl_h + (size_t)bb * CDIM * HW;
    if (MODE == 3) Bb = g_mva_h + (size_t)bb * CDIM * HW;

    float acc[4][4][4];
    #pragma unroll
    for (int mi = 0; mi < 4; mi++)
        #pragma unroll
        for (int ni = 0; ni < 4; ni++)
            #pragma unroll
            for (int e = 0; e < 4; e++) acc[mi][ni][e] = 0.f;

    const int nk = K >> 6;

    auto load_chunk = [&](int i) {
        const uint32_t base = sbase + (i & 1) * BUFB;
        const int kt = i * 64;
        #pragma unroll
        for (int l = 0; l < 4; l++) {
            int c = tid + l * 256;
            int r = c >> 3, s = c & 7;
            cp16(base + r * 128 + (((s ^ (r & 7))) << 4),
                 A + (size_t)(row0 + r) * K + kt + s * 8);
        }
        const __half* bsrc;
        if (MODE == 1) {
            int pj = __ldg(&g_idx[bb * TOPK + (kt >> 8)]);
            bsrc = g_xp_h + ((size_t)pj * RF + (kt & 255)) * HW;
        } else {
            bsrc = Bb + (size_t)kt * HW;
        }
        #pragma unroll
        for (int l = 0; l < 4; l++) {
            int c = tid + l * 256;
            int k = c >> 4, cn = c & 15;
            cp16(base + 16384 + k * 256 + ((cn & 8) << 4)
                      + (((cn & 7) ^ (k & 7)) << 4),
                 bsrc + (size_t)k * HW + cn * 8);
        }
        asm volatile("cp.async.commit_group;" ::: "memory");
    };

    load_chunk(0);
    for (int i = 0; i < nk; i++) {
        if (i + 1 < nk) {
            load_chunk(i + 1);
            asm volatile("cp.async.wait_group 1;" ::: "memory");
        } else {
            asm volatile("cp.async.wait_group 0;" ::: "memory");
        }
        __syncthreads();
        const uint32_t abase = sbase + (i & 1) * BUFB;
        const uint32_t bbase = abase + 16384;
        #pragma unroll
        for (int ks = 0; ks < 4; ks++) {
            const int k0 = ks * 16;
            uint32_t af[4][4], bf[4][2];
            const int arow = wm * 64 + (lane & 15);
            const int sch  = (k0 >> 3) + (lane >> 4);
            #pragma unroll
            for (int mi = 0; mi < 4; mi++) {
                int r = arow + mi * 16;
                ldsm_x4(af[mi], abase + r * 128 + (((sch ^ (r & 7)) & 7) << 4));
            }
            const int krow = k0 + (lane & 15);
            #pragma unroll
            for (int pr = 0; pr < 2; pr++) {
                int cn = wn * 4 + pr * 2 + (lane >> 4);
                uint32_t t[4];
                ldsm_x4t(t, bbase + krow * 256 + ((cn & 8) << 4)
                              + (((cn & 7) ^ (krow & 7)) << 4));
                bf[pr*2+0][0] = t[0]; bf[pr*2+0][1] = t[1];
                bf[pr*2+1][0] = t[2]; bf[pr*2+1][1] = t[3];
            }
            #pragma unroll
            for (int mi = 0; mi < 4; mi++)
                #pragma unroll
                for (int ni = 0; ni < 4; ni++)
                    mma16816(acc[mi][ni], af[mi], bf[ni]);
        }
        __syncthreads();
    }

    const int quad = lane >> 2, qi = lane & 3;

    if (MODE == 2) {
        __shared__ float sstat[128][4], qstat[128][4], msh[128], rsh[128];
        #pragma unroll
        for (int mi = 0; mi < 4; mi++)
            #pragma unroll
            for (int rh = 0; rh < 2; rh++) {
                float s = 0.f, q = 0.f;
                #pragma unroll
                for (int ni = 0; ni < 4; ni++) {
                    float v0 = acc[mi][ni][rh*2], v1 = acc[mi][ni][rh*2+1];
                    s += v0 + v1;
                    q = fmaf(v0, v0, fmaf(v1, v1, q));
                }
                s += __shfl_xor_sync(0xffffffffu, s, 1);
                q += __shfl_xor_sync(0xffffffffu, q, 1);
                s += __shfl_xor_sync(0xffffffffu, s, 2);
                q += __shfl_xor_sync(0xffffffffu, q, 2);
                if (qi == 0) {
                    int rt = wm * 64 + mi * 16 + quad + rh * 8;
                    sstat[rt][wn] = s;
                    qstat[rt][wn] = q;
                }
            }
        __syncthreads();
        if (tid < 128) {
            float s = sstat[tid][0] + sstat[tid][1] + sstat[tid][2] + sstat[tid][3];
            float q = qstat[tid][0] + qstat[tid][1] + qstat[tid][2] + qstat[tid][3];
            float mean = s * (1.0f/128.0f);
            float var  = q * (1.0f/128.0f) - mean * mean;
            msh[tid] = mean;
            rsh[tid] = rsqrtf(var + 1e-5f);
        }
        __syncthreads();
        __half* dst = g_mva_h + (size_t)bb * CDIM * HW;
        #pragma unroll
        for (int mi = 0; mi < 4; mi++)
            #pragma unroll
            for (int rh = 0; rh < 2; rh++) {
                int rt = wm * 64 + mi * 16 + quad + rh * 8;
                float mean = msh[rt], rstd = rsh[rt];
                int m = row0 + rt;
                #pragma unroll
                for (int ni = 0; ni < 4; ni++) {
                    int n = wn * 32 + ni * 8 + qi * 2;
                    float v0 = (acc[mi][ni][rh*2]   - mean) * rstd;
                    float v1 = (acc[mi][ni][rh*2+1] - mean) * rstd;
                    *(__half2*)(dst + (size_t)m * HW + n) = __floats2half2_rn(v0, v1);
                }
            }
    } else if (MODE == 1) {
        __half* dst = g_mvl_h + (size_t)bb * CDIM * HW;
        const float* xb = X + (size_t)bb * CDIM * HW;
        #pragma unroll
        for (int mi = 0; mi < 4; mi++)
            #pragma unroll
            for (int rh = 0; rh < 2; rh++) {
                int m = row0 + wm * 64 + mi * 16 + quad + rh * 8;
                #pragma unroll
                for (int ni = 0; ni < 4; ni++) {
                    int n = wn * 32 + ni * 8 + qi * 2;
                    float2 xv = *(const float2*)(xb + (size_t)m * HW + n);
                    float v0 = 0.5f * xv.x + COMPC * acc[mi][ni][rh*2];
                    float v1 = 0.5f * xv.y + COMPC * acc[mi][ni][rh*2+1];
                    v0 = v0 > 0.f ? v0 : 0.f;
                    v1 = v1 > 0.f ? v1 : 0.f;
                    *(__half2*)(dst + (size_t)m * HW + n) = __floats2half2_rn(v0, v1);
                }
            }
    } else {  // MODE 3
        const float* xb = X + (size_t)bb * CDIM * HW;
        float* ob = Out + (size_t)bb * CDIM * HW;
        #pragma unroll
        for (int mi = 0; mi < 4; mi++)
            #pragma unroll
            for (int rh = 0; rh < 2; rh++) {
                int m = row0 + wm * 64 + mi * 16 + quad + rh * 8;
                #pragma unroll
                for (int ni = 0; ni < 4; ni++) {
                    int n = wn * 32 + ni * 8 + qi * 2;
                    float2 xv = *(const float2*)(xb + (size_t)m * HW + n);
                    float s0 = 1.f / (1.f + __expf(-acc[mi][ni][rh*2]));
                    float s1 = 1.f / (1.f + __expf(-acc[mi][ni][rh*2+1]));
                    float2 o;
                    o.x = xv.x + xv.x * s0;
                    o.y = xv.y + xv.y * s1;
                    *(float2*)(ob + (size_t)m * HW + n) = o;
                }
            }
    }
}

// ---------------------------------------------------------------------------
extern "C" void kernel_launch(void* const* d_in, const int* in_sizes, int n_in,
                              void* d_out, int out_size)
{
    const float* x   = (const float*)d_in[0];
    const float* pr  = (const float*)d_in[1];
    const float* wrf = (const float*)d_in[2];
    const float* wmv = (const float*)d_in[3];
    const float* wrm = (const float*)d_in[4];
    const float* wfu = (const float*)d_in[5];
    float* out = (float*)d_out;

    // One-time handle setup (2 streams + 5 events -- proven footprint).
    static cudaStream_t s1 = nullptr, s2 = nullptr;
    static cudaEvent_t  e0 = nullptr, e1 = nullptr, ed = nullptr,
                        e2 = nullptr, e3 = nullptr;
    if (s1 == nullptr) {
        cudaStreamCreateWithFlags(&s1, cudaStreamNonBlocking);
        cudaStreamCreateWithFlags(&s2, cudaStreamNonBlocking);
        cudaEventCreateWithFlags(&e0, cudaEventDisableTiming);
        cudaEventCreateWithFlags(&e1, cudaEventDisableTiming);
        cudaEventCreateWithFlags(&ed, cudaEventDisableTiming);
        cudaEventCreateWithFlags(&e2, cudaEventDisableTiming);
        cudaEventCreateWithFlags(&e3, cudaEventDisableTiming);
        cudaFuncSetAttribute(gemm0_f32b,   cudaFuncAttributeMaxDynamicSharedMemorySize, G0_SMEM);
        cudaFuncSetAttribute(gemm_hmma<1>, cudaFuncAttributeMaxDynamicSharedMemorySize, SMEM128);
        cudaFuncSetAttribute(gemm_hmma<2>, cudaFuncAttributeMaxDynamicSharedMemorySize, SMEM128);
        cudaFuncSetAttribute(gemm_hmma<3>, cudaFuncAttributeMaxDynamicSharedMemorySize, SMEM128);
    }

    __half *wrf_h, *wmv_h, *wrm_h, *wfu_h;
    float *dot_p, *pn_p;
    cudaGetSymbolAddress((void**)&wrf_h,  g_wrf_h);
    cudaGetSymbolAddress((void**)&wmv_h,  g_wmv_h);
    cudaGetSymbolAddress((void**)&wrm_h,  g_wrm_h);
    cudaGetSymbolAddress((void**)&wfu_h,  g_wfu_h);
    cudaGetSymbolAddress((void**)&dot_p,  g_dot);
    cudaGetSymbolAddress((void**)&pn_p,   g_pn);

    // ---- fork ----
    cudaEventRecord(e0, 0);
    cudaStreamWaitEvent(s1, e0, 0);
    cudaStreamWaitEvent(s2, e0, 0);

    // Branch s1: wrf conversion, then gemm0 reading fp32 prototypes directly
    // (async-staged + SMEM convert) -- runs CONCURRENT with dist.
    f2h_kernel<<<(RF*CDIM/4 + 255)/256, 256, 0, s1>>>(wrf, wrf_h, RF*CDIM/4);
    gemm0_f32b<<<dim3(4, PN), 256, G0_SMEM, s1>>>(wrf_h, pr);
    cudaEventRecord(e1, s1);

    // Branch s2: weight conversions, then topk (after dist)
    {
        const int na4 = CDIM*TOPK*RF/4, nb4 = CDIM*CDIM/4, nc4 = CDIM*CDIM/4;
        f2h3_kernel<<<(na4 + nb4 + nc4 + 255)/256, 256, 0, s2>>>(
            wmv, wmv_h, na4, wrm, wrm_h, nb4, wfu, wfu_h, nc4);
    }

    // Main branch: zero accumulators, dist
    cudaMemsetAsync(dot_p, 0, NB*PN*sizeof(float), 0);
    cudaMemsetAsync(pn_p,  0, PN*sizeof(float),    0);
    dist_kernel<<<2048, 256>>>(x, pr);
    cudaEventRecord(ed, 0);

    // topk on s2 (needs dist results)
    cudaStreamWaitEvent(s2, ed, 0);
    topk_kernel<<<1, 16, 0, s2>>>();
    cudaEventRecord(e2, s2);

    // ---- join: gemm0 (s1) + topk/converts (s2) ----
    cudaStreamWaitEvent(0, e1, 0);
    cudaStreamWaitEvent(0, e2, 0);
    cudaEventRecord(e0, 0);   // reuse e0 as post-join readiness marker

    // ---- two pipelined chains of 8 samples (reuse s1; no new streams) ----
    cudaStreamWaitEvent(s1, e0, 0);
    gemm_hmma<1><<<dim3(16, NB/2), 256, SMEM128, s1>>>(wmv_h, x, nullptr, TOPK*RF, NB/2);
    gemm_hmma<2><<<dim3(16, NB/2), 256, SMEM128, s1>>>(wrm_h, nullptr, nullptr, CDIM, NB/2);
    gemm_hmma<3><<<dim3(16, NB/2), 256, SMEM128, s1>>>(wfu_h, x, out, CDIM, NB/2);
    cudaEventRecord(e3, s1);

    gemm_hmma<1><<<dim3(16, NB/2), 256, SMEM128>>>(wmv_h, x, nullptr, TOPK*RF, 0);
    gemm_hmma<2><<<dim3(16, NB/2), 256, SMEM128>>>(wrm_h, nullptr, nullptr, CDIM, 0);
    gemm_hmma<3><<<dim3(16, NB/2), 256, SMEM128>>>(wfu_h, x, out, CDIM, 0);

    cudaStreamWaitEvent(0, e3, 0);
}

// round 15
// speedup vs baseline: 1.0410x; 1.0410x over previous
#include <cuda_runtime.h>
#include <cuda_fp16.h>
#include <cstdint>

// Problem constants
#define NB    16
#define CDIM  2048
#define RF    256
#define HW    128
#define PN    64
#define TOPK  10
#define KF    (CDIM*HW)
#define COMPC (1.0f - 1.0f/262144.0f)   // calibration collapses: pos=0.5, comp=1-2^-18

// ---------------- device scratch (no allocations allowed) ----------------
__device__ float  g_dot[NB*PN];
__device__ float  g_pn [PN];
__device__ int    g_idx[NB*TOPK];
__device__ __half g_wrf_h[RF*CDIM];
__device__ __half g_wmv_h[CDIM*TOPK*RF];
__device__ __half g_wrm_h[CDIM*CDIM];
__device__ __half g_wfu_h[CDIM*CDIM];
__device__ __half g_xp_h [(size_t)PN*RF*HW];      // [p][rf][hw]
__device__ __half g_mvl_h[(size_t)NB*CDIM*HW];    // [b][c][hw]
__device__ __half g_mva_h[(size_t)NB*CDIM*HW];    // [b][c][hw]

// ---------------- helpers ----------------
__device__ __forceinline__ uint32_t s2u(const void* p) {
    return (uint32_t)__cvta_generic_to_shared(p);
}
__device__ __forceinline__ void cp16(uint32_t dst, const void* src) {
    asm volatile("cp.async.cg.shared.global [%0], [%1], 16;" :: "r"(dst), "l"(src));
}
__device__ __forceinline__ void ldsm_x4(uint32_t* r, uint32_t addr) {
    asm volatile("ldmatrix.sync.aligned.m8n8.x4.shared.b16 {%0,%1,%2,%3}, [%4];"
                 : "=r"(r[0]), "=r"(r[1]), "=r"(r[2]), "=r"(r[3]) : "r"(addr));
}
__device__ __forceinline__ void ldsm_x4t(uint32_t* r, uint32_t addr) {
    asm volatile("ldmatrix.sync.aligned.m8n8.x4.trans.shared.b16 {%0,%1,%2,%3}, [%4];"
                 : "=r"(r[0]), "=r"(r[1]), "=r"(r[2]), "=r"(r[3]) : "r"(addr));
}
__device__ __forceinline__ void mma16816(float* c, const uint32_t* a, const uint32_t* b) {
    asm volatile(
        "mma.sync.aligned.m16n8k16.row.col.f32.f16.f16.f32 "
        "{%0,%1,%2,%3}, {%4,%5,%6,%7}, {%8,%9}, {%0,%1,%2,%3};"
        : "+f"(c[0]), "+f"(c[1]), "+f"(c[2]), "+f"(c[3])
        : "r"(a[0]), "r"(a[1]), "r"(a[2]), "r"(a[3]), "r"(b[0]), "r"(b[1]));
}

// ---------------- stage 1: pairwise dots + ||p||^2 (register-blocked) -------
// Transposed SMEM tiles + 4n x 4p register tile per thread, k split across
// warp-quads. Inner loop: 8 conflict-free LDS per 16 FMA (was 5 LDS / 4 FMA).
__global__ __launch_bounds__(256) void dist_kernel(
    const float* __restrict__ x, const float* __restrict__ p)
{
    __shared__ float sxt[128][17];   // [k][n]
    __shared__ float spt[128][65];   // [k][p]  (reused as reduction scratch)
    const int t = threadIdx.x;
    const size_t k0 = (size_t)blockIdx.x * 128;

    // load x chunk transposed: 16 rows x 128 k
    #pragma unroll
    for (int l = 0; l < 2; l++) {
        int f = t + l * 256;
        int n = f >> 5, c4 = f & 31;
        float4 v = *(const float4*)(x + (size_t)n * KF + k0 + c4 * 4);
        sxt[c4*4+0][n] = v.x; sxt[c4*4+1][n] = v.y;
        sxt[c4*4+2][n] = v.z; sxt[c4*4+3][n] = v.w;
    }
    // load p chunk transposed: 64 rows x 128 k
    #pragma unroll
    for (int l = 0; l < 8; l++) {
        int f = t + l * 256;
        int q = f >> 5, c4 = f & 31;
        float4 v = *(const float4*)(p + (size_t)q * KF + k0 + c4 * 4);
        spt[c4*4+0][q] = v.x; spt[c4*4+1][q] = v.y;
        spt[c4*4+2][q] = v.z; spt[c4*4+3][q] = v.w;
    }
    __syncthreads();

    const int kq = t >> 6;            // k-quad: 32 k each
    const int u  = t & 63;
    const int n0 = (u >> 4) * 4;      // 4 consecutive n
    const int pq = u & 15;            // p_j = pq + 16j
    const bool do_pn = (n0 == 0);

    float acc[4][4];
    float accp[4] = {0.f, 0.f, 0.f, 0.f};
    #pragma unroll
    for (int i = 0; i < 4; i++)
        #pragma unroll
        for (int j = 0; j < 4; j++) acc[i][j] = 0.f;

    #pragma unroll 8
    for (int k = 0; k < 32; k++) {
        const int kk = kq * 32 + k;
        float xv[4], pv[4];
        #pragma unroll
        for (int i = 0; i < 4; i++) xv[i] = sxt[kk][n0 + i];
        #pragma unroll
        for (int j = 0; j < 4; j++) pv[j] = spt[kk][pq + 16*j];
        #pragma unroll
        for (int i = 0; i < 4; i++)
            #pragma unroll
            for (int j = 0; j < 4; j++)
                acc[i][j] = fmaf(xv[i], pv[j], acc[i][j]);
        if (do_pn)
            #pragma unroll
            for (int j = 0; j < 4; j++)
                accp[j] = fmaf(pv[j], pv[j], accp[j]);
    }
    __syncthreads();

    // reduce across k-quads via SMEM (reuse spt region: 8320 floats >= 4352)
    float* red = &spt[0][0];
    #pragma unroll
    for (int i = 0; i < 4; i++)
        #pragma unroll
        for (int j = 0; j < 4; j++)
            red[kq * 1024 + (n0 + i) * 64 + (pq + 16*j)] = acc[i][j];
    if (do_pn)
        #pragma unroll
        for (int j = 0; j < 4; j++)
            red[4096 + kq * 64 + (pq + 16*j)] = accp[j];
    __syncthreads();

    #pragma unroll
    for (int s = 0; s < 4; s++) {
        int slot = t * 4 + s;   // slot = n*64 + p == g_dot index
        float v = red[slot] + red[1024 + slot] + red[2048 + slot] + red[3072 + slot];
        atomicAdd(&g_dot[slot], v);
    }
    if (t < PN) {
        float v = red[4096 + t] + red[4096 + 64 + t]
                + red[4096 + 128 + t] + red[4096 + 192 + t];
        atomicAdd(&g_pn[t], v);
    }
}

// ---------------- stage 2: top-10 ----------------
__global__ void topk_kernel() {
    int n = threadIdx.x;
    if (n >= NB) return;
    float d[PN]; bool used[PN];
    for (int q = 0; q < PN; q++) {
        d[q] = g_pn[q] - 2.0f * g_dot[n*PN + q];
        used[q] = false;
    }
    for (int j = 0; j < TOPK; j++) {
        float best = 3.402823e38f; int bi = 0;
        for (int q = 0; q < PN; q++)
            if (!used[q] && d[q] < best) { best = d[q]; bi = q; }
        used[bi] = true;
        g_idx[n*TOPK + j] = bi;
    }
}

// ---------------- fp32 -> fp16 converts ----------------
__global__ void f2h_kernel(const float* __restrict__ in, __half* __restrict__ out, int n4) {
    int i = blockIdx.x * blockDim.x + threadIdx.x;
    if (i >= n4) return;
    float4 v = ((const float4*)in)[i];
    ((__half2*)out)[2*i]   = __floats2half2_rn(v.x, v.y);
    ((__half2*)out)[2*i+1] = __floats2half2_rn(v.z, v.w);
}
__global__ void f2h3_kernel(const float* __restrict__ a, __half* __restrict__ ah, int na4,
                            const float* __restrict__ b, __half* __restrict__ bh, int nb4,
                            const float* __restrict__ c, __half* __restrict__ ch, int nc4)
{
    int j = blockIdx.x * blockDim.x + threadIdx.x;
    const float* src; __half* dst;
    if (j < na4) { src = a; dst = ah; }
    else if ((j -= na4) < nb4) { src = b; dst = bh; }
    else if ((j -= nb4) < nc4) { src = c; dst = ch; }
    else return;
    float4 v = ((const float4*)src)[j];
    ((__half2*)dst)[2*j]   = __floats2half2_rn(v.x, v.y);
    ((__half2*)dst)[2*j+1] = __floats2half2_rn(v.z, v.w);
}

// ---------------- gemm0: 64x128 tile, fp32 B via SMEM staging + convert -----
#define G0_STAGE (8192 + 16384 + 32768)   // A + fp16 tile + fp32 staging
#define G0_SMEM  (2*G0_STAGE)             // 114688

__global__ __launch_bounds__(256, 2) void gemm0_f32b(
    const __half* __restrict__ A, const float* __restrict__ Bf)
{
    extern __shared__ char smem[];
    const uint32_t sbase = s2u(smem);
    const int tid  = threadIdx.x;
    const int lane = tid & 31;
    const int wid  = tid >> 5;
    const int wm   = wid >> 2;
    const int wn   = wid & 3;
    const int row0 = blockIdx.x * 64;
    const int bb   = blockIdx.y;
    const float* Bb = Bf + (size_t)bb * CDIM * HW;

    float acc[2][4][4];
    #pragma unroll
    for (int mi = 0; mi < 2; mi++)
        #pragma unroll
        for (int ni = 0; ni < 4; ni++)
            #pragma unroll
            for (int e = 0; e < 4; e++) acc[mi][ni][e] = 0.f;

    const int nk = CDIM >> 6;   // 32

    auto load_chunk = [&](int i) {
        const uint32_t base = sbase + (i & 1) * G0_STAGE;
        const int kt = i * 64;
        #pragma unroll
        for (int l = 0; l < 2; l++) {
            int c = tid + l * 256;
            int r = c >> 3, s = c & 7;
            cp16(base + r * 128 + (((s ^ (r & 7))) << 4),
                 A + (size_t)(row0 + r) * CDIM + kt + s * 8);
        }
        #pragma unroll
        for (int l = 0; l < 8; l++) {
            int c = tid + l * 256;
            int k = c >> 5, f4 = c & 31;
            cp16(base + 24576 + k * 512 + f4 * 16,
                 Bb + (size_t)(kt + k) * HW + f4 * 4);
        }
        asm volatile("cp.async.commit_group;" ::: "memory");
    };

    load_chunk(0);
    for (int i = 0; i < nk; i++) {
        if (i + 1 < nk) {
            load_chunk(i + 1);
            asm volatile("cp.async.wait_group 1;" ::: "memory");
        } else {
            asm volatile("cp.async.wait_group 0;" ::: "memory");
        }
        __syncthreads();
        const char* stg = smem + (i & 1) * G0_STAGE + 24576;
        char*       til = smem + (i & 1) * G0_STAGE + 8192;
        #pragma unroll
        for (int l = 0; l < 4; l++) {
            int c = tid + l * 256;
            int k = c >> 4, cn = c & 15;
            const float4* src = (const float4*)(stg + k * 512 + cn * 32);
            float4 v0 = src[0], v1 = src[1];
            __half2 h[4];
            h[0] = __floats2half2_rn(v0.x, v0.y);
            h[1] = __floats2half2_rn(v0.z, v0.w);
            h[2] = __floats2half2_rn(v1.x, v1.y);
            h[3] = __floats2half2_rn(v1.z, v1.w);
            *(uint4*)(til + k * 256 + ((cn & 8) << 4)
                          + (((cn & 7) ^ (k & 7)) << 4)) = *(uint4*)h;
        }
        __syncthreads();

        const uint32_t abase = sbase + (i & 1) * G0_STAGE;
        const uint32_t bbase = abase + 8192;
        #pragma unroll
        for (int ks = 0; ks < 4; ks++) {
            const int k0 = ks * 16;
            uint32_t af[2][4], bf[4][2];
            const int arow = wm * 32 + (lane & 15);
            const int sch  = (k0 >> 3) + (lane >> 4);
            #pragma unroll
            for (int mi = 0; mi < 2; mi++) {
                int r = arow + mi * 16;
                ldsm_x4(af[mi], abase + r * 128 + (((sch ^ (r & 7)) & 7) << 4));
            }
            const int krow = k0 + (lane & 15);
            #pragma unroll
            for (int pr = 0; pr < 2; pr++) {
                int cn = wn * 4 + pr * 2 + (lane >> 4);
                uint32_t t[4];
                ldsm_x4t(t, bbase + krow * 256 + ((cn & 8) << 4)
                              + (((cn & 7) ^ (krow & 7)) << 4));
                bf[pr*2+0][0] = t[0]; bf[pr*2+0][1] = t[1];
                bf[pr*2+1][0] = t[2]; bf[pr*2+1][1] = t[3];
            }
            #pragma unroll
            for (int mi = 0; mi < 2; mi++)
                #pragma unroll
                for (int ni = 0; ni < 4; ni++)
                    mma16816(acc[mi][ni], af[mi], bf[ni]);
        }
        __syncthreads();
    }

    const int quad = lane >> 2, qi = lane & 3;
    __half* dst = g_xp_h + (size_t)bb * RF * HW;
    #pragma unroll
    for (int mi = 0; mi < 2; mi++)
        #pragma unroll
        for (int rh = 0; rh < 2; rh++) {
            int m = row0 + wm * 32 + mi * 16 + quad + rh * 8;
            #pragma unroll
            for (int ni = 0; ni < 4; ni++) {
                int n = wn * 32 + ni * 8 + qi * 2;
                *(__half2*)(dst + (size_t)m * HW + n) =
                    __floats2half2_rn(acc[mi][ni][rh*2], acc[mi][ni][rh*2+1]);
            }
        }
}

// ---------------- chain HMMA GEMM: 128x128 tile (champion, unchanged) -------
#define BUFB 32768
#define SMEM128 (2*BUFB)

template<int MODE>
__global__ __launch_bounds__(256, 2) void gemm_hmma(
    const __half* __restrict__ A,
    const float* __restrict__ X, float* __restrict__ Out, int K, int bb0)
{
    extern __shared__ char smem[];
    const uint32_t sbase = s2u(smem);
    const int tid  = threadIdx.x;
    const int lane = tid & 31;
    const int wid  = tid >> 5;
    const int wm   = wid >> 2;
    const int wn   = wid & 3;
    const int row0 = blockIdx.x * 128;
    const int bb   = blockIdx.y + bb0;

    const __half* Bb = nullptr;
    if (MODE == 2) Bb = g_mvl_h + (size_t)bb * CDIM * HW;
    if (MODE == 3) Bb = g_mva_h + (size_t)bb * CDIM * HW;

    float acc[4][4][4];
    #pragma unroll
    for (int mi = 0; mi < 4; mi++)
        #pragma unroll
        for (int ni = 0; ni < 4; ni++)
            #pragma unroll
            for (int e = 0; e < 4; e++) acc[mi][ni][e] = 0.f;

    const int nk = K >> 6;

    auto load_chunk = [&](int i) {
        const uint32_t base = sbase + (i & 1) * BUFB;
        const int kt = i * 64;
        #pragma unroll
        for (int l = 0; l < 4; l++) {
            int c = tid + l * 256;
            int r = c >> 3, s = c & 7;
            cp16(base + r * 128 + (((s ^ (r & 7))) << 4),
                 A + (size_t)(row0 + r) * K + kt + s * 8);
        }
        const __half* bsrc;
        if (MODE == 1) {
            int pj = __ldg(&g_idx[bb * TOPK + (kt >> 8)]);
            bsrc = g_xp_h + ((size_t)pj * RF + (kt & 255)) * HW;
        } else {
            bsrc = Bb + (size_t)kt * HW;
        }
        #pragma unroll
        for (int l = 0; l < 4; l++) {
            int c = tid + l * 256;
            int k = c >> 4, cn = c & 15;
            cp16(base + 16384 + k * 256 + ((cn & 8) << 4)
                      + (((cn & 7) ^ (k & 7)) << 4),
                 bsrc + (size_t)k * HW + cn * 8);
        }
        asm volatile("cp.async.commit_group;" ::: "memory");
    };

    load_chunk(0);
    for (int i = 0; i < nk; i++) {
        if (i + 1 < nk) {
            load_chunk(i + 1);
            asm volatile("cp.async.wait_group 1;" ::: "memory");
        } else {
            asm volatile("cp.async.wait_group 0;" ::: "memory");
        }
        __syncthreads();
        const uint32_t abase = sbase + (i & 1) * BUFB;
        const uint32_t bbase = abase + 16384;
        #pragma unroll
        for (int ks = 0; ks < 4; ks++) {
            const int k0 = ks * 16;
            uint32_t af[4][4], bf[4][2];
            const int arow = wm * 64 + (lane & 15);
            const int sch  = (k0 >> 3) + (lane >> 4);
            #pragma unroll
            for (int mi = 0; mi < 4; mi++) {
                int r = arow + mi * 16;
                ldsm_x4(af[mi], abase + r * 128 + (((sch ^ (r & 7)) & 7) << 4));
            }
            const int krow = k0 + (lane & 15);
            #pragma unroll
            for (int pr = 0; pr < 2; pr++) {
                int cn = wn * 4 + pr * 2 + (lane >> 4);
                uint32_t t[4];
                ldsm_x4t(t, bbase + krow * 256 + ((cn & 8) << 4)
                              + (((cn & 7) ^ (krow & 7)) << 4));
                bf[pr*2+0][0] = t[0]; bf[pr*2+0][1] = t[1];
                bf[pr*2+1][0] = t[2]; bf[pr*2+1][1] = t[3];
            }
            #pragma unroll
            for (int mi = 0; mi < 4; mi++)
                #pragma unroll
                for (int ni = 0; ni < 4; ni++)
                    mma16816(acc[mi][ni], af[mi], bf[ni]);
        }
        __syncthreads();
    }

    const int quad = lane >> 2, qi = lane & 3;

    if (MODE == 2) {
        __shared__ float sstat[128][4], qstat[128][4], msh[128], rsh[128];
        #pragma unroll
        for (int mi = 0; mi < 4; mi++)
            #pragma unroll
            for (int rh = 0; rh < 2; rh++) {
                float s = 0.f, q = 0.f;
                #pragma unroll
                for (int ni = 0; ni < 4; ni++) {
                    float v0 = acc[mi][ni][rh*2], v1 = acc[mi][ni][rh*2+1];
                    s += v0 + v1;
                    q = fmaf(v0, v0, fmaf(v1, v1, q));
                }
                s += __shfl_xor_sync(0xffffffffu, s, 1);
                q += __shfl_xor_sync(0xffffffffu, q, 1);
                s += __shfl_xor_sync(0xffffffffu, s, 2);
                q += __shfl_xor_sync(0xffffffffu, q, 2);
                if (qi == 0) {
                    int rt = wm * 64 + mi * 16 + quad + rh * 8;
                    sstat[rt][wn] = s;
                    qstat[rt][wn] = q;
                }
            }
        __syncthreads();
        if (tid < 128) {
            float s = sstat[tid][0] + sstat[tid][1] + sstat[tid][2] + sstat[tid][3];
            float q = qstat[tid][0] + qstat[tid][1] + qstat[tid][2] + qstat[tid][3];
            float mean = s * (1.0f/128.0f);
            float var  = q * (1.0f/128.0f) - mean * mean;
            msh[tid] = mean;
            rsh[tid] = rsqrtf(var + 1e-5f);
        }
        __syncthreads();
        __half* dst = g_mva_h + (size_t)bb * CDIM * HW;
        #pragma unroll
        for (int mi = 0; mi < 4; mi++)
            #pragma unroll
            for (int rh = 0; rh < 2; rh++) {
                int rt = wm * 64 + mi * 16 + quad + rh * 8;
                float mean = msh[rt], rstd = rsh[rt];
                int m = row0 + rt;
                #pragma unroll
                for (int ni = 0; ni < 4; ni++) {
                    int n = wn * 32 + ni * 8 + qi * 2;
                    float v0 = (acc[mi][ni][rh*2]   - mean) * rstd;
                    float v1 = (acc[mi][ni][rh*2+1] - mean) * rstd;
                    *(__half2*)(dst + (size_t)m * HW + n) = __floats2half2_rn(v0, v1);
                }
            }
    } else if (MODE == 1) {
        __half* dst = g_mvl_h + (size_t)bb * CDIM * HW;
        const float* xb = X + (size_t)bb * CDIM * HW;
        #pragma unroll
        for (int mi = 0; mi < 4; mi++)
            #pragma unroll
            for (int rh = 0; rh < 2; rh++) {
                int m = row0 + wm * 64 + mi * 16 + quad + rh * 8;
                #pragma unroll
                for (int ni = 0; ni < 4; ni++) {
                    int n = wn * 32 + ni * 8 + qi * 2;
                    float2 xv = *(const float2*)(xb + (size_t)m * HW + n);
                    float v0 = 0.5f * xv.x + COMPC * acc[mi][ni][rh*2];
                    float v1 = 0.5f * xv.y + COMPC * acc[mi][ni][rh*2+1];
                    v0 = v0 > 0.f ? v0 : 0.f;
                    v1 = v1 > 0.f ? v1 : 0.f;
                    *(__half2*)(dst + (size_t)m * HW + n) = __floats2half2_rn(v0, v1);
                }
            }
    } else {  // MODE 3
        const float* xb = X + (size_t)bb * CDIM * HW;
        float* ob = Out + (size_t)bb * CDIM * HW;
        #pragma unroll
        for (int mi = 0; mi < 4; mi++)
            #pragma unroll
            for (int rh = 0; rh < 2; rh++) {
                int m = row0 + wm * 64 + mi * 16 + quad + rh * 8;
                #pragma unroll
                for (int ni = 0; ni < 4; ni++) {
                    int n = wn * 32 + ni * 8 + qi * 2;
                    float2 xv = *(const float2*)(xb + (size_t)m * HW + n);
                    float s0 = 1.f / (1.f + __expf(-acc[mi][ni][rh*2]));
                    float s1 = 1.f / (1.f + __expf(-acc[mi][ni][rh*2+1]));
                    float2 o;
                    o.x = xv.x + xv.x * s0;
                    o.y = xv.y + xv.y * s1;
                    *(float2*)(ob + (size_t)m * HW + n) = o;
                }
            }
    }
}

// ---------------------------------------------------------------------------
extern "C" void kernel_launch(void* const* d_in, const int* in_sizes, int n_in,
                              void* d_out, int out_size)
{
    const float* x   = (const float*)d_in[0];
    const float* pr  = (const float*)d_in[1];
    const float* wrf = (const float*)d_in[2];
    const float* wmv = (const float*)d_in[3];
    const float* wrm = (const float*)d_in[4];
    const float* wfu = (const float*)d_in[5];
    float* out = (float*)d_out;

    // One-time handle setup (2 streams + 5 events -- proven footprint).
    static cudaStream_t s1 = nullptr, s2 = nullptr;
    static cudaEvent_t  e0 = nullptr, e1 = nullptr, ed = nullptr,
                        e2 = nullptr, e3 = nullptr;
    if (s1 == nullptr) {
        cudaStreamCreateWithFlags(&s1, cudaStreamNonBlocking);
        cudaStreamCreateWithFlags(&s2, cudaStreamNonBlocking);
        cudaEventCreateWithFlags(&e0, cudaEventDisableTiming);
        cudaEventCreateWithFlags(&e1, cudaEventDisableTiming);
        cudaEventCreateWithFlags(&ed, cudaEventDisableTiming);
        cudaEventCreateWithFlags(&e2, cudaEventDisableTiming);
        cudaEventCreateWithFlags(&e3, cudaEventDisableTiming);
        cudaFuncSetAttribute(gemm0_f32b,   cudaFuncAttributeMaxDynamicSharedMemorySize, G0_SMEM);
        cudaFuncSetAttribute(gemm_hmma<1>, cudaFuncAttributeMaxDynamicSharedMemorySize, SMEM128);
        cudaFuncSetAttribute(gemm_hmma<2>, cudaFuncAttributeMaxDynamicSharedMemorySize, SMEM128);
        cudaFuncSetAttribute(gemm_hmma<3>, cudaFuncAttributeMaxDynamicSharedMemorySize, SMEM128);
    }

    __half *wrf_h, *wmv_h, *wrm_h, *wfu_h;
    float *dot_p, *pn_p;
    cudaGetSymbolAddress((void**)&wrf_h,  g_wrf_h);
    cudaGetSymbolAddress((void**)&wmv_h,  g_wmv_h);
    cudaGetSymbolAddress((void**)&wrm_h,  g_wrm_h);
    cudaGetSymbolAddress((void**)&wfu_h,  g_wfu_h);
    cudaGetSymbolAddress((void**)&dot_p,  g_dot);
    cudaGetSymbolAddress((void**)&pn_p,   g_pn);

    // ---- fork ----
    cudaEventRecord(e0, 0);
    cudaStreamWaitEvent(s1, e0, 0);
    cudaStreamWaitEvent(s2, e0, 0);

    // Branch s1: wrf conversion, then gemm0 (fp32 B) -- concurrent with dist.
    f2h_kernel<<<(RF*CDIM/4 + 255)/256, 256, 0, s1>>>(wrf, wrf_h, RF*CDIM/4);
    gemm0_f32b<<<dim3(4, PN), 256, G0_SMEM, s1>>>(wrf_h, pr);
    cudaEventRecord(e1, s1);

    // Branch s2: weight conversions, then topk (after dist)
    {
        const int na4 = CDIM*TOPK*RF/4, nb4 = CDIM*CDIM/4, nc4 = CDIM*CDIM/4;
        f2h3_kernel<<<(na4 + nb4 + nc4 + 255)/256, 256, 0, s2>>>(
            wmv, wmv_h, na4, wrm, wrm_h, nb4, wfu, wfu_h, nc4);
    }

    // Main branch: zero accumulators, dist
    cudaMemsetAsync(dot_p, 0, NB*PN*sizeof(float), 0);
    cudaMemsetAsync(pn_p,  0, PN*sizeof(float),    0);
    dist_kernel<<<2048, 256>>>(x, pr);
    cudaEventRecord(ed, 0);

    // topk on s2 (needs dist results)
    cudaStreamWaitEvent(s2, ed, 0);
    topk_kernel<<<1, 16, 0, s2>>>();
    cudaEventRecord(e2, s2);

    // ---- join: gemm0 (s1) + topk/converts (s2) ----
    cudaStreamWaitEvent(0, e1, 0);
    cudaStreamWaitEvent(0, e2, 0);
    cudaEventRecord(e0, 0);   // reuse e0 as post-join readiness marker

    // ---- two pipelined chains of 8 samples (reuse s1; no new streams) ----
    cudaStreamWaitEvent(s1, e0, 0);
    gemm_hmma<1><<<dim3(16, NB/2), 256, SMEM128, s1>>>(wmv_h, x, nullptr, TOPK*RF, NB/2);
    gemm_hmma<2><<<dim3(16, NB/2), 256, SMEM128, s1>>>(wrm_h, nullptr, nullptr, CDIM, NB/2);
    gemm_hmma<3><<<dim3(16, NB/2), 256, SMEM128, s1>>>(wfu_h, x, out, CDIM, NB/2);
    cudaEventRecord(e3, s1);

    gemm_hmma<1><<<dim3(16, NB/2), 256, SMEM128>>>(wmv_h, x, nullptr, TOPK*RF, 0);
    gemm_hmma<2><<<dim3(16, NB/2), 256, SMEM128>>>(wrm_h, nullptr, nullptr, CDIM, 0);
    gemm_hmma<3><<<dim3(16, NB/2), 256, SMEM128>>>(wfu_h, x, out, CDIM, 0);

    cudaStreamWaitEvent(0, e3, 0);
}

// round 16
// speedup vs baseline: 1.1737x; 1.1275x over previous
#include <cuda_runtime.h>
#include <cuda_fp16.h>
#include <cstdint>

// Problem constants
#define NB    16
#define CDIM  2048
#define RF    256
#define HW    128
#define PN    64
#define TOPK  10
#define KF    (CDIM*HW)
#define COMPC (1.0f - 1.0f/262144.0f)   // calibration collapses: pos=0.5, comp=1-2^-18

// ---------------- device scratch (no allocations allowed) ----------------
__device__ float  g_dot[NB*PN];
__device__ float  g_pn [PN];
__device__ int    g_idx[NB*TOPK];
__device__ __half g_wrf_h[RF*CDIM];
__device__ __half g_wmv_h[CDIM*TOPK*RF];
__device__ __half g_wrm_h[CDIM*CDIM];
__device__ __half g_wfu_h[CDIM*CDIM];
__device__ __half g_xp_h [(size_t)PN*RF*HW];      // [p][rf][hw]
__device__ __half g_mvl_h[(size_t)NB*CDIM*HW];    // [b][c][hw]
__device__ __half g_mva_h[(size_t)NB*CDIM*HW];    // [b][c][hw]

// ---------------- helpers ----------------
__device__ __forceinline__ uint32_t s2u(const void* p) {
    return (uint32_t)__cvta_generic_to_shared(p);
}
__device__ __forceinline__ void cp16(uint32_t dst, const void* src) {
    asm volatile("cp.async.cg.shared.global [%0], [%1], 16;" :: "r"(dst), "l"(src));
}
__device__ __forceinline__ void ldsm_x4(uint32_t* r, uint32_t addr) {
    asm volatile("ldmatrix.sync.aligned.m8n8.x4.shared.b16 {%0,%1,%2,%3}, [%4];"
                 : "=r"(r[0]), "=r"(r[1]), "=r"(r[2]), "=r"(r[3]) : "r"(addr));
}
__device__ __forceinline__ void ldsm_x4t(uint32_t* r, uint32_t addr) {
    asm volatile("ldmatrix.sync.aligned.m8n8.x4.trans.shared.b16 {%0,%1,%2,%3}, [%4];"
                 : "=r"(r[0]), "=r"(r[1]), "=r"(r[2]), "=r"(r[3]) : "r"(addr));
}
__device__ __forceinline__ void mma16816(float* c, const uint32_t* a, const uint32_t* b) {
    asm volatile(
        "mma.sync.aligned.m16n8k16.row.col.f32.f16.f16.f32 "
        "{%0,%1,%2,%3}, {%4,%5,%6,%7}, {%8,%9}, {%0,%1,%2,%3};"
        : "+f"(c[0]), "+f"(c[1]), "+f"(c[2]), "+f"(c[3])
        : "r"(a[0]), "r"(a[1]), "r"(a[2]), "r"(a[3]), "r"(b[0]), "r"(b[1]));
}

// ---------------- stage 1: dots + ||p||^2, 8 chunks/block, low atomic fan-in
// 256 blocks x 8 k-chunks. Register accumulators persist across chunks ->
// atomics drop 8x (2.2M -> 278K RED ops; the old per-address serialization at
// the LTS atomic ALU was the hidden ~70us floor). Global loads for chunk i+1
// are register-prefetched during compute of chunk i.
#define DCH 8
__global__ __launch_bounds__(256) void dist_kernel(
    const float* __restrict__ x, const float* __restrict__ p)
{
    __shared__ float sxt[128][17];   // [k][n]
    __shared__ float spt[128][65];   // [k][p]  (reused as reduction scratch)
    const int t = threadIdx.x;
    const size_t kbase = (size_t)blockIdx.x * (DCH * 128);

    const int kq = t >> 6;            // k-quad: 32 k each
    const int u  = t & 63;
    const int n0 = (u >> 4) * 4;      // 4 consecutive n
    const int pq = u & 15;            // p_j = pq + 16j
    const bool do_pn = (n0 == 0);

    float acc[4][4];
    float accp[4] = {0.f, 0.f, 0.f, 0.f};
    #pragma unroll
    for (int i = 0; i < 4; i++)
        #pragma unroll
        for (int j = 0; j < 4; j++) acc[i][j] = 0.f;

    float4 xr[2], pr[8];
    auto load_regs = [&](int ci) {
        const size_t k0 = kbase + (size_t)ci * 128;
        #pragma unroll
        for (int l = 0; l < 2; l++) {
            int f = t + l * 256;
            int n = f >> 5, c4 = f & 31;
            xr[l] = *(const float4*)(x + (size_t)n * KF + k0 + c4 * 4);
        }
        #pragma unroll
        for (int l = 0; l < 8; l++) {
            int f = t + l * 256;
            int q = f >> 5, c4 = f & 31;
            pr[l] = *(const float4*)(p + (size_t)q * KF + k0 + c4 * 4);
        }
    };

    load_regs(0);
    for (int ci = 0; ci < DCH; ci++) {
        // stage registers -> transposed SMEM
        #pragma unroll
        for (int l = 0; l < 2; l++) {
            int f = t + l * 256;
            int n = f >> 5, c4 = f & 31;
            sxt[c4*4+0][n] = xr[l].x; sxt[c4*4+1][n] = xr[l].y;
            sxt[c4*4+2][n] = xr[l].z; sxt[c4*4+3][n] = xr[l].w;
        }
        #pragma unroll
        for (int l = 0; l < 8; l++) {
            int f = t + l * 256;
            int q = f >> 5, c4 = f & 31;
            spt[c4*4+0][q] = pr[l].x; spt[c4*4+1][q] = pr[l].y;
            spt[c4*4+2][q] = pr[l].z; spt[c4*4+3][q] = pr[l].w;
        }
        __syncthreads();

        if (ci + 1 < DCH) load_regs(ci + 1);   // LDGs land during compute

        #pragma unroll 8
        for (int k = 0; k < 32; k++) {
            const int kk = kq * 32 + k;
            float xv[4], pv[4];
            #pragma unroll
            for (int i = 0; i < 4; i++) xv[i] = sxt[kk][n0 + i];
            #pragma unroll
            for (int j = 0; j < 4; j++) pv[j] = spt[kk][pq + 16*j];
            #pragma unroll
            for (int i = 0; i < 4; i++)
                #pragma unroll
                for (int j = 0; j < 4; j++)
                    acc[i][j] = fmaf(xv[i], pv[j], acc[i][j]);
            if (do_pn)
                #pragma unroll
                for (int j = 0; j < 4; j++)
                    accp[j] = fmaf(pv[j], pv[j], accp[j]);
        }
        __syncthreads();   // before next iteration's STS overwrites tiles
    }

    // reduce across k-quads via SMEM (reuse spt region: 8320 floats >= 4352)
    float* red = &spt[0][0];
    #pragma unroll
    for (int i = 0; i < 4; i++)
        #pragma unroll
        for (int j = 0; j < 4; j++)
            red[kq * 1024 + (n0 + i) * 64 + (pq + 16*j)] = acc[i][j];
    if (do_pn)
        #pragma unroll
        for (int j = 0; j < 4; j++)
            red[4096 + kq * 64 + (pq + 16*j)] = accp[j];
    __syncthreads();

    #pragma unroll
    for (int s = 0; s < 4; s++) {
        int slot = t * 4 + s;   // slot = n*64 + p == g_dot index
        float v = red[slot] + red[1024 + slot] + red[2048 + slot] + red[3072 + slot];
        atomicAdd(&g_dot[slot], v);
    }
    if (t < PN) {
        float v = red[4096 + t] + red[4096 + 64 + t]
                + red[4096 + 128 + t] + red[4096 + 192 + t];
        atomicAdd(&g_pn[t], v);
    }
}

// ---------------- stage 2: top-10 ----------------
__global__ void topk_kernel() {
    int n = threadIdx.x;
    if (n >= NB) return;
    float d[PN]; bool used[PN];
    for (int q = 0; q < PN; q++) {
        d[q] = g_pn[q] - 2.0f * g_dot[n*PN + q];
        used[q] = false;
    }
    for (int j = 0; j < TOPK; j++) {
        float best = 3.402823e38f; int bi = 0;
        for (int q = 0; q < PN; q++)
            if (!used[q] && d[q] < best) { best = d[q]; bi = q; }
        used[bi] = true;
        g_idx[n*TOPK + j] = bi;
    }
}

// ---------------- fp32 -> fp16 converts ----------------
__global__ void f2h_kernel(const float* __restrict__ in, __half* __restrict__ out, int n4) {
    int i = blockIdx.x * blockDim.x + threadIdx.x;
    if (i >= n4) return;
    float4 v = ((const float4*)in)[i];
    ((__half2*)out)[2*i]   = __floats2half2_rn(v.x, v.y);
    ((__half2*)out)[2*i+1] = __floats2half2_rn(v.z, v.w);
}
__global__ void f2h3_kernel(const float* __restrict__ a, __half* __restrict__ ah, int na4,
                            const float* __restrict__ b, __half* __restrict__ bh, int nb4,
                            const float* __restrict__ c, __half* __restrict__ ch, int nc4)
{
    int j = blockIdx.x * blockDim.x + threadIdx.x;
    const float* src; __half* dst;
    if (j < na4) { src = a; dst = ah; }
    else if ((j -= na4) < nb4) { src = b; dst = bh; }
    else if ((j -= nb4) < nc4) { src = c; dst = ch; }
    else return;
    float4 v = ((const float4*)src)[j];
    ((__half2*)dst)[2*j]   = __floats2half2_rn(v.x, v.y);
    ((__half2*)dst)[2*j+1] = __floats2half2_rn(v.z, v.w);
}

// ---------------- gemm0: 64x128 tile, fp32 B via SMEM staging + convert -----
#define G0_STAGE (8192 + 16384 + 32768)   // A + fp16 tile + fp32 staging
#define G0_SMEM  (2*G0_STAGE)             // 114688

__global__ __launch_bounds__(256, 2) void gemm0_f32b(
    const __half* __restrict__ A, const float* __restrict__ Bf)
{
    extern __shared__ char smem[];
    const uint32_t sbase = s2u(smem);
    const int tid  = threadIdx.x;
    const int lane = tid & 31;
    const int wid  = tid >> 5;
    const int wm   = wid >> 2;
    const int wn   = wid & 3;
    const int row0 = blockIdx.x * 64;
    const int bb   = blockIdx.y;
    const float* Bb = Bf + (size_t)bb * CDIM * HW;

    float acc[2][4][4];
    #pragma unroll
    for (int mi = 0; mi < 2; mi++)
        #pragma unroll
        for (int ni = 0; ni < 4; ni++)
            #pragma unroll
            for (int e = 0; e < 4; e++) acc[mi][ni][e] = 0.f;

    const int nk = CDIM >> 6;   // 32

    auto load_chunk = [&](int i) {
        const uint32_t base = sbase + (i & 1) * G0_STAGE;
        const int kt = i * 64;
        #pragma unroll
        for (int l = 0; l < 2; l++) {
            int c = tid + l * 256;
            int r = c >> 3, s = c & 7;
            cp16(base + r * 128 + (((s ^ (r & 7))) << 4),
                 A + (size_t)(row0 + r) * CDIM + kt + s * 8);
        }
        #pragma unroll
        for (int l = 0; l < 8; l++) {
            int c = tid + l * 256;
            int k = c >> 5, f4 = c & 31;
            cp16(base + 24576 + k * 512 + f4 * 16,
                 Bb + (size_t)(kt + k) * HW + f4 * 4);
        }
        asm volatile("cp.async.commit_group;" ::: "memory");
    };

    load_chunk(0);
    for (int i = 0; i < nk; i++) {
        if (i + 1 < nk) {
            load_chunk(i + 1);
            asm volatile("cp.async.wait_group 1;" ::: "memory");
        } else {
            asm volatile("cp.async.wait_group 0;" ::: "memory");
        }
        __syncthreads();
        const char* stg = smem + (i & 1) * G0_STAGE + 24576;
        char*       til = smem + (i & 1) * G0_STAGE + 8192;
        #pragma unroll
        for (int l = 0; l < 4; l++) {
            int c = tid + l * 256;
            int k = c >> 4, cn = c & 15;
            const float4* src = (const float4*)(stg + k * 512 + cn * 32);
            float4 v0 = src[0], v1 = src[1];
            __half2 h[4];
            h[0] = __floats2half2_rn(v0.x, v0.y);
            h[1] = __floats2half2_rn(v0.z, v0.w);
            h[2] = __floats2half2_rn(v1.x, v1.y);
            h[3] = __floats2half2_rn(v1.z, v1.w);
            *(uint4*)(til + k * 256 + ((cn & 8) << 4)
                          + (((cn & 7) ^ (k & 7)) << 4)) = *(uint4*)h;
        }
        __syncthreads();

        const uint32_t abase = sbase + (i & 1) * G0_STAGE;
        const uint32_t bbase = abase + 8192;
        #pragma unroll
        for (int ks = 0; ks < 4; ks++) {
            const int k0 = ks * 16;
            uint32_t af[2][4], bf[4][2];
            const int arow = wm * 32 + (lane & 15);
            const int sch  = (k0 >> 3) + (lane >> 4);
            #pragma unroll
            for (int mi = 0; mi < 2; mi++) {
                int r = arow + mi * 16;
                ldsm_x4(af[mi], abase + r * 128 + (((sch ^ (r & 7)) & 7) << 4));
            }
            const int krow = k0 + (lane & 15);
            #pragma unroll
            for (int pr = 0; pr < 2; pr++) {
                int cn = wn * 4 + pr * 2 + (lane >> 4);
                uint32_t t[4];
                ldsm_x4t(t, bbase + krow * 256 + ((cn & 8) << 4)
                              + (((cn & 7) ^ (krow & 7)) << 4));
                bf[pr*2+0][0] = t[0]; bf[pr*2+0][1] = t[1];
                bf[pr*2+1][0] = t[2]; bf[pr*2+1][1] = t[3];
            }
            #pragma unroll
            for (int mi = 0; mi < 2; mi++)
                #pragma unroll
                for (int ni = 0; ni < 4; ni++)
                    mma16816(acc[mi][ni], af[mi], bf[ni]);
        }
        __syncthreads();
    }

    const int quad = lane >> 2, qi = lane & 3;
    __half* dst = g_xp_h + (size_t)bb * RF * HW;
    #pragma unroll
    for (int mi = 0; mi < 2; mi++)
        #pragma unroll
        for (int rh = 0; rh < 2; rh++) {
            int m = row0 + wm * 32 + mi * 16 + quad + rh * 8;
            #pragma unroll
            for (int ni = 0; ni < 4; ni++) {
                int n = wn * 32 + ni * 8 + qi * 2;
                *(__half2*)(dst + (size_t)m * HW + n) =
                    __floats2half2_rn(acc[mi][ni][rh*2], acc[mi][ni][rh*2+1]);
            }
        }
}

// ---------------- chain HMMA GEMM: 128x128 tile (champion, unchanged) -------
#define BUFB 32768
#define SMEM128 (2*BUFB)

template<int MODE>
__global__ __launch_bounds__(256, 2) void gemm_hmma(
    const __half* __restrict__ A,
    const float* __restrict__ X, float* __restrict__ Out, int K, int bb0)
{
    extern __shared__ char smem[];
    const uint32_t sbase = s2u(smem);
    const int tid  = threadIdx.x;
    const int lane = tid & 31;
    const int wid  = tid >> 5;
    const int wm   = wid >> 2;
    const int wn   = wid & 3;
    const int row0 = blockIdx.x * 128;
    const int bb   = blockIdx.y + bb0;

    const __half* Bb = nullptr;
    if (MODE == 2) Bb = g_mvl_h + (size_t)bb * CDIM * HW;
    if (MODE == 3) Bb = g_mva_h + (size_t)bb * CDIM * HW;

    float acc[4][4][4];
    #pragma unroll
    for (int mi = 0; mi < 4; mi++)
        #pragma unroll
        for (int ni = 0; ni < 4; ni++)
            #pragma unroll
            for (int e = 0; e < 4; e++) acc[mi][ni][e] = 0.f;

    const int nk = K >> 6;

    auto load_chunk = [&](int i) {
        const uint32_t base = sbase + (i & 1) * BUFB;
        const int kt = i * 64;
        #pragma unroll
        for (int l = 0; l < 4; l++) {
            int c = tid + l * 256;
            int r = c >> 3, s = c & 7;
            cp16(base + r * 128 + (((s ^ (r & 7))) << 4),
                 A + (size_t)(row0 + r) * K + kt + s * 8);
        }
        const __half* bsrc;
        if (MODE == 1) {
            int pj = __ldg(&g_idx[bb * TOPK + (kt >> 8)]);
            bsrc = g_xp_h + ((size_t)pj * RF + (kt & 255)) * HW;
        } else {
            bsrc = Bb + (size_t)kt * HW;
        }
        #pragma unroll
        for (int l = 0; l < 4; l++) {
            int c = tid + l * 256;
            int k = c >> 4, cn = c & 15;
            cp16(base + 16384 + k * 256 + ((cn & 8) << 4)
                      + (((cn & 7) ^ (k & 7)) << 4),
                 bsrc + (size_t)k * HW + cn * 8);
        }
        asm volatile("cp.async.commit_group;" ::: "memory");
    };

    load_chunk(0);
    for (int i = 0; i < nk; i++) {
        if (i + 1 < nk) {
            load_chunk(i + 1);
            asm volatile("cp.async.wait_group 1;" ::: "memory");
        } else {
            asm volatile("cp.async.wait_group 0;" ::: "memory");
        }
        __syncthreads();
        const uint32_t abase = sbase + (i & 1) * BUFB;
        const uint32_t bbase = abase + 16384;
        #pragma unroll
        for (int ks = 0; ks < 4; ks++) {
            const int k0 = ks * 16;
            uint32_t af[4][4], bf[4][2];
            const int arow = wm * 64 + (lane & 15);
            const int sch  = (k0 >> 3) + (lane >> 4);
            #pragma unroll
            for (int mi = 0; mi < 4; mi++) {
                int r = arow + mi * 16;
                ldsm_x4(af[mi], abase + r * 128 + (((sch ^ (r & 7)) & 7) << 4));
            }
            const int krow = k0 + (lane & 15);
            #pragma unroll
            for (int pr = 0; pr < 2; pr++) {
                int cn = wn * 4 + pr * 2 + (lane >> 4);
                uint32_t t[4];
                ldsm_x4t(t, bbase + krow * 256 + ((cn & 8) << 4)
                              + (((cn & 7) ^ (krow & 7)) << 4));
                bf[pr*2+0][0] = t[0]; bf[pr*2+0][1] = t[1];
                bf[pr*2+1][0] = t[2]; bf[pr*2+1][1] = t[3];
            }
            #pragma unroll
            for (int mi = 0; mi < 4; mi++)
                #pragma unroll
                for (int ni = 0; ni < 4; ni++)
                    mma16816(acc[mi][ni], af[mi], bf[ni]);
        }
        __syncthreads();
    }

    const int quad = lane >> 2, qi = lane & 3;

    if (MODE == 2) {
        __shared__ float sstat[128][4], qstat[128][4], msh[128], rsh[128];
        #pragma unroll
        for (int mi = 0; mi < 4; mi++)
            #pragma unroll
            for (int rh = 0; rh < 2; rh++) {
                float s = 0.f, q = 0.f;
                #pragma unroll
                for (int ni = 0; ni < 4; ni++) {
                    float v0 = acc[mi][ni][rh*2], v1 = acc[mi][ni][rh*2+1];
                    s += v0 + v1;
                    q = fmaf(v0, v0, fmaf(v1, v1, q));
                }
                s += __shfl_xor_sync(0xffffffffu, s, 1);
                q += __shfl_xor_sync(0xffffffffu, q, 1);
                s += __shfl_xor_sync(0xffffffffu, s, 2);
                q += __shfl_xor_sync(0xffffffffu, q, 2);
                if (qi == 0) {
                    int rt = wm * 64 + mi * 16 + quad + rh * 8;
                    sstat[rt][wn] = s;
                    qstat[rt][wn] = q;
                }
            }
        __syncthreads();
        if (tid < 128) {
            float s = sstat[tid][0] + sstat[tid][1] + sstat[tid][2] + sstat[tid][3];
            float q = qstat[tid][0] + qstat[tid][1] + qstat[tid][2] + qstat[tid][3];
            float mean = s * (1.0f/128.0f);
            float var  = q * (1.0f/128.0f) - mean * mean;
            msh[tid] = mean;
            rsh[tid] = rsqrtf(var + 1e-5f);
        }
        __syncthreads();
        __half* dst = g_mva_h + (size_t)bb * CDIM * HW;
        #pragma unroll
        for (int mi = 0; mi < 4; mi++)
            #pragma unroll
            for (int rh = 0; rh < 2; rh++) {
                int rt = wm * 64 + mi * 16 + quad + rh * 8;
                float mean = msh[rt], rstd = rsh[rt];
                int m = row0 + rt;
                #pragma unroll
                for (int ni = 0; ni < 4; ni++) {
                    int n = wn * 32 + ni * 8 + qi * 2;
                    float v0 = (acc[mi][ni][rh*2]   - mean) * rstd;
                    float v1 = (acc[mi][ni][rh*2+1] - mean) * rstd;
                    *(__half2*)(dst + (size_t)m * HW + n) = __floats2half2_rn(v0, v1);
                }
            }
    } else if (MODE == 1) {
        __half* dst = g_mvl_h + (size_t)bb * CDIM * HW;
        const float* xb = X + (size_t)bb * CDIM * HW;
        #pragma unroll
        for (int mi = 0; mi < 4; mi++)
            #pragma unroll
            for (int rh = 0; rh < 2; rh++) {
                int m = row0 + wm * 64 + mi * 16 + quad + rh * 8;
                #pragma unroll
                for (int ni = 0; ni < 4; ni++) {
                    int n = wn * 32 + ni * 8 + qi * 2;
                    float2 xv = *(const float2*)(xb + (size_t)m * HW + n);
                    float v0 = 0.5f * xv.x + COMPC * acc[mi][ni][rh*2];
                    float v1 = 0.5f * xv.y + COMPC * acc[mi][ni][rh*2+1];
                    v0 = v0 > 0.f ? v0 : 0.f;
                    v1 = v1 > 0.f ? v1 : 0.f;
                    *(__half2*)(dst + (size_t)m * HW + n) = __floats2half2_rn(v0, v1);
                }
            }
    } else {  // MODE 3
        const float* xb = X + (size_t)bb * CDIM * HW;
        float* ob = Out + (size_t)bb * CDIM * HW;
        #pragma unroll
        for (int mi = 0; mi < 4; mi++)
            #pragma unroll
            for (int rh = 0; rh < 2; rh++) {
                int m = row0 + wm * 64 + mi * 16 + quad + rh * 8;
                #pragma unroll
                for (int ni = 0; ni < 4; ni++) {
                    int n = wn * 32 + ni * 8 + qi * 2;
                    float2 xv = *(const float2*)(xb + (size_t)m * HW + n);
                    float s0 = 1.f / (1.f + __expf(-acc[mi][ni][rh*2]));
                    float s1 = 1.f / (1.f + __expf(-acc[mi][ni][rh*2+1]));
                    float2 o;
                    o.x = xv.x + xv.x * s0;
                    o.y = xv.y + xv.y * s1;
                    *(float2*)(ob + (size_t)m * HW + n) = o;
                }
            }
    }
}

// ---------------------------------------------------------------------------
extern "C" void kernel_launch(void* const* d_in, const int* in_sizes, int n_in,
                              void* d_out, int out_size)
{
    const float* x   = (const float*)d_in[0];
    const float* pr  = (const float*)d_in[1];
    const float* wrf = (const float*)d_in[2];
    const float* wmv = (const float*)d_in[3];
    const float* wrm = (const float*)d_in[4];
    const float* wfu = (const float*)d_in[5];
    float* out = (float*)d_out;

    // One-time handle setup (2 streams + 5 events -- proven footprint).
    static cudaStream_t s1 = nullptr, s2 = nullptr;
    static cudaEvent_t  e0 = nullptr, e1 = nullptr, ed = nullptr,
                        e2 = nullptr, e3 = nullptr;
    if (s1 == nullptr) {
        cudaStreamCreateWithFlags(&s1, cudaStreamNonBlocking);
        cudaStreamCreateWithFlags(&s2, cudaStreamNonBlocking);
        cudaEventCreateWithFlags(&e0, cudaEventDisableTiming);
        cudaEventCreateWithFlags(&e1, cudaEventDisableTiming);
        cudaEventCreateWithFlags(&ed, cudaEventDisableTiming);
        cudaEventCreateWithFlags(&e2, cudaEventDisableTiming);
        cudaEventCreateWithFlags(&e3, cudaEventDisableTiming);
        cudaFuncSetAttribute(gemm0_f32b,   cudaFuncAttributeMaxDynamicSharedMemorySize, G0_SMEM);
        cudaFuncSetAttribute(gemm_hmma<1>, cudaFuncAttributeMaxDynamicSharedMemorySize, SMEM128);
        cudaFuncSetAttribute(gemm_hmma<2>, cudaFuncAttributeMaxDynamicSharedMemorySize, SMEM128);
        cudaFuncSetAttribute(gemm_hmma<3>, cudaFuncAttributeMaxDynamicSharedMemorySize, SMEM128);
    }

    __half *wrf_h, *wmv_h, *wrm_h, *wfu_h;
    float *dot_p, *pn_p;
    cudaGetSymbolAddress((void**)&wrf_h,  g_wrf_h);
    cudaGetSymbolAddress((void**)&wmv_h,  g_wmv_h);
    cudaGetSymbolAddress((void**)&wrm_h,  g_wrm_h);
    cudaGetSymbolAddress((void**)&wfu_h,  g_wfu_h);
    cudaGetSymbolAddress((void**)&dot_p,  g_dot);
    cudaGetSymbolAddress((void**)&pn_p,   g_pn);

    // ---- fork ----
    cudaEventRecord(e0, 0);
    cudaStreamWaitEvent(s1, e0, 0);
    cudaStreamWaitEvent(s2, e0, 0);

    // Branch s1: wrf conversion, then gemm0 (fp32 B) -- concurrent with dist.
    f2h_kernel<<<(RF*CDIM/4 + 255)/256, 256, 0, s1>>>(wrf, wrf_h, RF*CDIM/4);
    gemm0_f32b<<<dim3(4, PN), 256, G0_SMEM, s1>>>(wrf_h, pr);
    cudaEventRecord(e1, s1);

    // Branch s2: weight conversions, then topk (after dist)
    {
        const int na4 = CDIM*TOPK*RF/4, nb4 = CDIM*CDIM/4, nc4 = CDIM*CDIM/4;
        f2h3_kernel<<<(na4 + nb4 + nc4 + 255)/256, 256, 0, s2>>>(
            wmv, wmv_h, na4, wrm, wrm_h, nb4, wfu, wfu_h, nc4);
    }

    // Main branch: zero accumulators, dist (256 blocks x 8 chunks)
    cudaMemsetAsync(dot_p, 0, NB*PN*sizeof(float), 0);
    cudaMemsetAsync(pn_p,  0, PN*sizeof(float),    0);
    dist_kernel<<<256, 256>>>(x, pr);
    cudaEventRecord(ed, 0);

    // topk on s2 (needs dist results)
    cudaStreamWaitEvent(s2, ed, 0);
    topk_kernel<<<1, 16, 0, s2>>>();
    cudaEventRecord(e2, s2);

    // ---- join: gemm0 (s1) + topk/converts (s2) ----
    cudaStreamWaitEvent(0, e1, 0);
    cudaStreamWaitEvent(0, e2, 0);
    cudaEventRecord(e0, 0);   // reuse e0 as post-join readiness marker

    // ---- two pipelined chains of 8 samples (reuse s1; no new streams) ----
    cudaStreamWaitEvent(s1, e0, 0);
    gemm_hmma<1><<<dim3(16, NB/2), 256, SMEM128, s1>>>(wmv_h, x, nullptr, TOPK*RF, NB/2);
    gemm_hmma<2><<<dim3(16, NB/2), 256, SMEM128, s1>>>(wrm_h, nullptr, nullptr, CDIM, NB/2);
    gemm_hmma<3><<<dim3(16, NB/2), 256, SMEM128, s1>>>(wfu_h, x, out, CDIM, NB/2);
    cudaEventRecord(e3, s1);

    gemm_hmma<1><<<dim3(16, NB/2), 256, SMEM128>>>(wmv_h, x, nullptr, TOPK*RF, 0);
    gemm_hmma<2><<<dim3(16, NB/2), 256, SMEM128>>>(wrm_h, nullptr, nullptr, CDIM, 0);
    gemm_hmma<3><<<dim3(16, NB/2), 256, SMEM128>>>(wfu_h, x, out, CDIM, 0);

    cudaStreamWaitEvent(0, e3, 0);
}

// round 17
// speedup vs baseline: 1.2047x; 1.0264x over previous
#include <cuda_runtime.h>
#include <cuda_fp16.h>
#include <cstdint>

// Problem constants
#define NB    16
#define CDIM  2048
#define RF    256
#define HW    128
#define PN    64
#define TOPK  10
#define KF    (CDIM*HW)
#define COMPC (1.0f - 1.0f/262144.0f)   // calibration collapses: pos=0.5, comp=1-2^-18

// ---------------- device scratch (no allocations allowed) ----------------
__device__ float  g_dot[NB*PN];
__device__ float  g_pn [PN];
__device__ int    g_idx[NB*TOPK];
__device__ __half g_wrf_h[RF*CDIM];
__device__ __half g_wmv_h[CDIM*TOPK*RF];
__device__ __half g_wrm_h[CDIM*CDIM];
__device__ __half g_wfu_h[CDIM*CDIM];
__device__ __half g_xp_h [(size_t)PN*RF*HW];      // [p][rf][hw]
__device__ __half g_mvl_h[(size_t)NB*CDIM*HW];    // [b][c][hw]
__device__ __half g_mva_h[(size_t)NB*CDIM*HW];    // [b][c][hw]

// ---------------- helpers ----------------
__device__ __forceinline__ uint32_t s2u(const void* p) {
    return (uint32_t)__cvta_generic_to_shared(p);
}
__device__ __forceinline__ void cp16(uint32_t dst, const void* src) {
    asm volatile("cp.async.cg.shared.global [%0], [%1], 16;" :: "r"(dst), "l"(src));
}
__device__ __forceinline__ void ldsm_x4(uint32_t* r, uint32_t addr) {
    asm volatile("ldmatrix.sync.aligned.m8n8.x4.shared.b16 {%0,%1,%2,%3}, [%4];"
                 : "=r"(r[0]), "=r"(r[1]), "=r"(r[2]), "=r"(r[3]) : "r"(addr));
}
__device__ __forceinline__ void ldsm_x4t(uint32_t* r, uint32_t addr) {
    asm volatile("ldmatrix.sync.aligned.m8n8.x4.trans.shared.b16 {%0,%1,%2,%3}, [%4];"
                 : "=r"(r[0]), "=r"(r[1]), "=r"(r[2]), "=r"(r[3]) : "r"(addr));
}
__device__ __forceinline__ void mma16816(float* c, const uint32_t* a, const uint32_t* b) {
    asm volatile(
        "mma.sync.aligned.m16n8k16.row.col.f32.f16.f16.f32 "
        "{%0,%1,%2,%3}, {%4,%5,%6,%7}, {%8,%9}, {%0,%1,%2,%3};"
        : "+f"(c[0]), "+f"(c[1]), "+f"(c[2]), "+f"(c[3])
        : "r"(a[0]), "r"(a[1]), "r"(a[2]), "r"(a[3]), "r"(b[0]), "r"(b[1]));
}

// ---------------- stage 1: dots + ||p||^2, 4 chunks/block, 512 blocks -------
// 512 blocks fill the chip (296 resident slots at 2 CTA/SM); register
// accumulators persist across 4 k-chunks -> 512 atomic writers per address
// (cheap; R16 established the fan-in model). LDGs for chunk i+1 prefetch
// into registers during compute of chunk i.
#define DCH 4
__global__ __launch_bounds__(256) void dist_kernel(
    const float* __restrict__ x, const float* __restrict__ p)
{
    __shared__ float sxt[128][17];   // [k][n]
    __shared__ float spt[128][65];   // [k][p]  (reused as reduction scratch)
    const int t = threadIdx.x;
    const size_t kbase = (size_t)blockIdx.x * (DCH * 128);

    const int kq = t >> 6;            // k-quad: 32 k each
    const int u  = t & 63;
    const int n0 = (u >> 4) * 4;      // 4 consecutive n
    const int pq = u & 15;            // p_j = pq + 16j
    const bool do_pn = (n0 == 0);

    float acc[4][4];
    float accp[4] = {0.f, 0.f, 0.f, 0.f};
    #pragma unroll
    for (int i = 0; i < 4; i++)
        #pragma unroll
        for (int j = 0; j < 4; j++) acc[i][j] = 0.f;

    float4 xr[2], pr[8];
    auto load_regs = [&](int ci) {
        const size_t k0 = kbase + (size_t)ci * 128;
        #pragma unroll
        for (int l = 0; l < 2; l++) {
            int f = t + l * 256;
            int n = f >> 5, c4 = f & 31;
            xr[l] = *(const float4*)(x + (size_t)n * KF + k0 + c4 * 4);
        }
        #pragma unroll
        for (int l = 0; l < 8; l++) {
            int f = t + l * 256;
            int q = f >> 5, c4 = f & 31;
            pr[l] = *(const float4*)(p + (size_t)q * KF + k0 + c4 * 4);
        }
    };

    load_regs(0);
    for (int ci = 0; ci < DCH; ci++) {
        #pragma unroll
        for (int l = 0; l < 2; l++) {
            int f = t + l * 256;
            int n = f >> 5, c4 = f & 31;
            sxt[c4*4+0][n] = xr[l].x; sxt[c4*4+1][n] = xr[l].y;
            sxt[c4*4+2][n] = xr[l].z; sxt[c4*4+3][n] = xr[l].w;
        }
        #pragma unroll
        for (int l = 0; l < 8; l++) {
            int f = t + l * 256;
            int q = f >> 5, c4 = f & 31;
            spt[c4*4+0][q] = pr[l].x; spt[c4*4+1][q] = pr[l].y;
            spt[c4*4+2][q] = pr[l].z; spt[c4*4+3][q] = pr[l].w;
        }
        __syncthreads();

        if (ci + 1 < DCH) load_regs(ci + 1);   // LDGs land during compute

        #pragma unroll 8
        for (int k = 0; k < 32; k++) {
            const int kk = kq * 32 + k;
            float xv[4], pv[4];
            #pragma unroll
            for (int i = 0; i < 4; i++) xv[i] = sxt[kk][n0 + i];
            #pragma unroll
            for (int j = 0; j < 4; j++) pv[j] = spt[kk][pq + 16*j];
            #pragma unroll
            for (int i = 0; i < 4; i++)
                #pragma unroll
                for (int j = 0; j < 4; j++)
                    acc[i][j] = fmaf(xv[i], pv[j], acc[i][j]);
            if (do_pn)
                #pragma unroll
                for (int j = 0; j < 4; j++)
                    accp[j] = fmaf(pv[j], pv[j], accp[j]);
        }
        __syncthreads();
    }

    // reduce across k-quads via SMEM (reuse spt region: 8320 floats >= 4352)
    float* red = &spt[0][0];
    #pragma unroll
    for (int i = 0; i < 4; i++)
        #pragma unroll
        for (int j = 0; j < 4; j++)
            red[kq * 1024 + (n0 + i) * 64 + (pq + 16*j)] = acc[i][j];
    if (do_pn)
        #pragma unroll
        for (int j = 0; j < 4; j++)
            red[4096 + kq * 64 + (pq + 16*j)] = accp[j];
    __syncthreads();

    #pragma unroll
    for (int s = 0; s < 4; s++) {
        int slot = t * 4 + s;
        float v = red[slot] + red[1024 + slot] + red[2048 + slot] + red[3072 + slot];
        atomicAdd(&g_dot[slot], v);
    }
    if (t < PN) {
        float v = red[4096 + t] + red[4096 + 64 + t]
                + red[4096 + 128 + t] + red[4096 + 192 + t];
        atomicAdd(&g_pn[t], v);
    }
}

// ---------------- stage 2: top-10, warp-parallel (1 warp per sample) --------
// Lane l owns prototypes l and l+32. 10 rounds of bfly min-reduce with
// smaller-index tie-break == the serial stable selection exactly.
__global__ void topk_kernel() {
    const int n    = threadIdx.x >> 5;
    const int lane = threadIdx.x & 31;
    if (n >= NB) return;
    float d0 = g_pn[lane]      - 2.0f * g_dot[n*PN + lane];
    float d1 = g_pn[lane + 32] - 2.0f * g_dot[n*PN + lane + 32];
    #pragma unroll
    for (int j = 0; j < TOPK; j++) {
        // local best of the two (tie -> smaller index)
        float bv; int bi;
        if (d1 < d0) { bv = d1; bi = lane + 32; }
        else         { bv = d0; bi = lane; }
        // warp bfly reduce (tie -> smaller index); all lanes converge
        #pragma unroll
        for (int off = 16; off >= 1; off >>= 1) {
            float ov = __shfl_xor_sync(0xffffffffu, bv, off);
            int   oi = __shfl_xor_sync(0xffffffffu, bi, off);
            if (ov < bv || (ov == bv && oi < bi)) { bv = ov; bi = oi; }
        }
        if (lane == 0) g_idx[n*TOPK + j] = bi;
        // mark winner used
        if (bi == lane)      d0 = 3.402823e38f;
        if (bi == lane + 32) d1 = 3.402823e38f;
    }
}

// ---------------- fp32 -> fp16 converts ----------------
__global__ void f2h_kernel(const float* __restrict__ in, __half* __restrict__ out, int n4) {
    int i = blockIdx.x * blockDim.x + threadIdx.x;
    if (i >= n4) return;
    float4 v = ((const float4*)in)[i];
    ((__half2*)out)[2*i]   = __floats2half2_rn(v.x, v.y);
    ((__half2*)out)[2*i+1] = __floats2half2_rn(v.z, v.w);
}
__global__ void f2h3_kernel(const float* __restrict__ a, __half* __restrict__ ah, int na4,
                            const float* __restrict__ b, __half* __restrict__ bh, int nb4,
                            const float* __restrict__ c, __half* __restrict__ ch, int nc4)
{
    int j = blockIdx.x * blockDim.x + threadIdx.x;
    const float* src; __half* dst;
    if (j < na4) { src = a; dst = ah; }
    else if ((j -= na4) < nb4) { src = b; dst = bh; }
    else if ((j -= nb4) < nc4) { src = c; dst = ch; }
    else return;
    float4 v = ((const float4*)src)[j];
    ((__half2*)dst)[2*j]   = __floats2half2_rn(v.x, v.y);
    ((__half2*)dst)[2*j+1] = __floats2half2_rn(v.z, v.w);
}

// ---------------- gemm0: 64x128 tile, fp32 B via SMEM staging + convert -----
#define G0_STAGE (8192 + 16384 + 32768)
#define G0_SMEM  (2*G0_STAGE)

__global__ __launch_bounds__(256, 2) void gemm0_f32b(
    const __half* __restrict__ A, const float* __restrict__ Bf)
{
    extern __shared__ char smem[];
    const uint32_t sbase = s2u(smem);
    const int tid  = threadIdx.x;
    const int lane = tid & 31;
    const int wid  = tid >> 5;
    const int wm   = wid >> 2;
    const int wn   = wid & 3;
    const int row0 = blockIdx.x * 64;
    const int bb   = blockIdx.y;
    const float* Bb = Bf + (size_t)bb * CDIM * HW;

    float acc[2][4][4];
    #pragma unroll
    for (int mi = 0; mi < 2; mi++)
        #pragma unroll
        for (int ni = 0; ni < 4; ni++)
            #pragma unroll
            for (int e = 0; e < 4; e++) acc[mi][ni][e] = 0.f;

    const int nk = CDIM >> 6;

    auto load_chunk = [&](int i) {
        const uint32_t base = sbase + (i & 1) * G0_STAGE;
        const int kt = i * 64;
        #pragma unroll
        for (int l = 0; l < 2; l++) {
            int c = tid + l * 256;
            int r = c >> 3, s = c & 7;
            cp16(base + r * 128 + (((s ^ (r & 7))) << 4),
                 A + (size_t)(row0 + r) * CDIM + kt + s * 8);
        }
        #pragma unroll
        for (int l = 0; l < 8; l++) {
            int c = tid + l * 256;
            int k = c >> 5, f4 = c & 31;
            cp16(base + 24576 + k * 512 + f4 * 16,
                 Bb + (size_t)(kt + k) * HW + f4 * 4);
        }
        asm volatile("cp.async.commit_group;" ::: "memory");
    };

    load_chunk(0);
    for (int i = 0; i < nk; i++) {
        if (i + 1 < nk) {
            load_chunk(i + 1);
            asm volatile("cp.async.wait_group 1;" ::: "memory");
        } else {
            asm volatile("cp.async.wait_group 0;" ::: "memory");
        }
        __syncthreads();
        const char* stg = smem + (i & 1) * G0_STAGE + 24576;
        char*       til = smem + (i & 1) * G0_STAGE + 8192;
        #pragma unroll
        for (int l = 0; l < 4; l++) {
            int c = tid + l * 256;
            int k = c >> 4, cn = c & 15;
            const float4* src = (const float4*)(stg + k * 512 + cn * 32);
            float4 v0 = src[0], v1 = src[1];
            __half2 h[4];
            h[0] = __floats2half2_rn(v0.x, v0.y);
            h[1] = __floats2half2_rn(v0.z, v0.w);
            h[2] = __floats2half2_rn(v1.x, v1.y);
            h[3] = __floats2half2_rn(v1.z, v1.w);
            *(uint4*)(til + k * 256 + ((cn & 8) << 4)
                          + (((cn & 7) ^ (k & 7)) << 4)) = *(uint4*)h;
        }
        __syncthreads();

        const uint32_t abase = sbase + (i & 1) * G0_STAGE;
        const uint32_t bbase = abase + 8192;
        #pragma unroll
        for (int ks = 0; ks < 4; ks++) {
            const int k0 = ks * 16;
            uint32_t af[2][4], bf[4][2];
            const int arow = wm * 32 + (lane & 15);
            const int sch  = (k0 >> 3) + (lane >> 4);
            #pragma unroll
            for (int mi = 0; mi < 2; mi++) {
                int r = arow + mi * 16;
                ldsm_x4(af[mi], abase + r * 128 + (((sch ^ (r & 7)) & 7) << 4));
            }
            const int krow = k0 + (lane & 15);
            #pragma unroll
            for (int pr = 0; pr < 2; pr++) {
                int cn = wn * 4 + pr * 2 + (lane >> 4);
                uint32_t t[4];
                ldsm_x4t(t, bbase + krow * 256 + ((cn & 8) << 4)
                              + (((cn & 7) ^ (krow & 7)) << 4));
                bf[pr*2+0][0] = t[0]; bf[pr*2+0][1] = t[1];
                bf[pr*2+1][0] = t[2]; bf[pr*2+1][1] = t[3];
            }
            #pragma unroll
            for (int mi = 0; mi < 2; mi++)
                #pragma unroll
                for (int ni = 0; ni < 4; ni++)
                    mma16816(acc[mi][ni], af[mi], bf[ni]);
        }
        __syncthreads();
    }

    const int quad = lane >> 2, qi = lane & 3;
    __half* dst = g_xp_h + (size_t)bb * RF * HW;
    #pragma unroll
    for (int mi = 0; mi < 2; mi++)
        #pragma unroll
        for (int rh = 0; rh < 2; rh++) {
            int m = row0 + wm * 32 + mi * 16 + quad + rh * 8;
            #pragma unroll
            for (int ni = 0; ni < 4; ni++) {
                int n = wn * 32 + ni * 8 + qi * 2;
                *(__half2*)(dst + (size_t)m * HW + n) =
                    __floats2half2_rn(acc[mi][ni][rh*2], acc[mi][ni][rh*2+1]);
            }
        }
}

// ---------------- chain HMMA GEMM: 128x128 tile (champion, unchanged) -------
#define BUFB 32768
#define SMEM128 (2*BUFB)

template<int MODE>
__global__ __launch_bounds__(256, 2) void gemm_hmma(
    const __half* __restrict__ A,
    const float* __restrict__ X, float* __restrict__ Out, int K, int bb0)
{
    extern __shared__ char smem[];
    const uint32_t sbase = s2u(smem);
    const int tid  = threadIdx.x;
    const int lane = tid & 31;
    const int wid  = tid >> 5;
    const int wm   = wid >> 2;
    const int wn   = wid & 3;
    const int row0 = blockIdx.x * 128;
    const int bb   = blockIdx.y + bb0;

    const __half* Bb = nullptr;
    if (MODE == 2) Bb = g_mvl_h + (size_t)bb * CDIM * HW;
    if (MODE == 3) Bb = g_mva_h + (size_t)bb * CDIM * HW;

    float acc[4][4][4];
    #pragma unroll
    for (int mi = 0; mi < 4; mi++)
        #pragma unroll
        for (int ni = 0; ni < 4; ni++)
            #pragma unroll
            for (int e = 0; e < 4; e++) acc[mi][ni][e] = 0.f;

    const int nk = K >> 6;

    auto load_chunk = [&](int i) {
        const uint32_t base = sbase + (i & 1) * BUFB;
        const int kt = i * 64;
        #pragma unroll
        for (int l = 0; l < 4; l++) {
            int c = tid + l * 256;
            int r = c >> 3, s = c & 7;
            cp16(base + r * 128 + (((s ^ (r & 7))) << 4),
                 A + (size_t)(row0 + r) * K + kt + s * 8);
        }
        const __half* bsrc;
        if (MODE == 1) {
            int pj = __ldg(&g_idx[bb * TOPK + (kt >> 8)]);
            bsrc = g_xp_h + ((size_t)pj * RF + (kt & 255)) * HW;
        } else {
            bsrc = Bb + (size_t)kt * HW;
        }
        #pragma unroll
        for (int l = 0; l < 4; l++) {
            int c = tid + l * 256;
            int k = c >> 4, cn = c & 15;
            cp16(base + 16384 + k * 256 + ((cn & 8) << 4)
                      + (((cn & 7) ^ (k & 7)) << 4),
                 bsrc + (size_t)k * HW + cn * 8);
        }
        asm volatile("cp.async.commit_group;" ::: "memory");
    };

    load_chunk(0);
    for (int i = 0; i < nk; i++) {
        if (i + 1 < nk) {
            load_chunk(i + 1);
            asm volatile("cp.async.wait_group 1;" ::: "memory");
        } else {
            asm volatile("cp.async.wait_group 0;" ::: "memory");
        }
        __syncthreads();
        const uint32_t abase = sbase + (i & 1) * BUFB;
        const uint32_t bbase = abase + 16384;
        #pragma unroll
        for (int ks = 0; ks < 4; ks++) {
            const int k0 = ks * 16;
            uint32_t af[4][4], bf[4][2];
            const int arow = wm * 64 + (lane & 15);
            const int sch  = (k0 >> 3) + (lane >> 4);
            #pragma unroll
            for (int mi = 0; mi < 4; mi++) {
                int r = arow + mi * 16;
                ldsm_x4(af[mi], abase + r * 128 + (((sch ^ (r & 7)) & 7) << 4));
            }
            const int krow = k0 + (lane & 15);
            #pragma unroll
            for (int pr = 0; pr < 2; pr++) {
                int cn = wn * 4 + pr * 2 + (lane >> 4);
                uint32_t t[4];
                ldsm_x4t(t, bbase + krow * 256 + ((cn & 8) << 4)
                              + (((cn & 7) ^ (krow & 7)) << 4));
                bf[pr*2+0][0] = t[0]; bf[pr*2+0][1] = t[1];
                bf[pr*2+1][0] = t[2]; bf[pr*2+1][1] = t[3];
            }
            #pragma unroll
            for (int mi = 0; mi < 4; mi++)
                #pragma unroll
                for (int ni = 0; ni < 4; ni++)
                    mma16816(acc[mi][ni], af[mi], bf[ni]);
        }
        __syncthreads();
    }

    const int quad = lane >> 2, qi = lane & 3;

    if (MODE == 2) {
        __shared__ float sstat[128][4], qstat[128][4], msh[128], rsh[128];
        #pragma unroll
        for (int mi = 0; mi < 4; mi++)
            #pragma unroll
            for (int rh = 0; rh < 2; rh++) {
                float s = 0.f, q = 0.f;
                #pragma unroll
                for (int ni = 0; ni < 4; ni++) {
                    float v0 = acc[mi][ni][rh*2], v1 = acc[mi][ni][rh*2+1];
                    s += v0 + v1;
                    q = fmaf(v0, v0, fmaf(v1, v1, q));
                }
                s += __shfl_xor_sync(0xffffffffu, s, 1);
                q += __shfl_xor_sync(0xffffffffu, q, 1);
                s += __shfl_xor_sync(0xffffffffu, s, 2);
                q += __shfl_xor_sync(0xffffffffu, q, 2);
                if (qi == 0) {
                    int rt = wm * 64 + mi * 16 + quad + rh * 8;
                    sstat[rt][wn] = s;
                    qstat[rt][wn] = q;
                }
            }
        __syncthreads();
        if (tid < 128) {
            float s = sstat[tid][0] + sstat[tid][1] + sstat[tid][2] + sstat[tid][3];
            float q = qstat[tid][0] + qstat[tid][1] + qstat[tid][2] + qstat[tid][3];
            float mean = s * (1.0f/128.0f);
            float var  = q * (1.0f/128.0f) - mean * mean;
            msh[tid] = mean;
            rsh[tid] = rsqrtf(var + 1e-5f);
        }
        __syncthreads();
        __half* dst = g_mva_h + (size_t)bb * CDIM * HW;
        #pragma unroll
        for (int mi = 0; mi < 4; mi++)
            #pragma unroll
            for (int rh = 0; rh < 2; rh++) {
                int rt = wm * 64 + mi * 16 + quad + rh * 8;
                float mean = msh[rt], rstd = rsh[rt];
                int m = row0 + rt;
                #pragma unroll
                for (int ni = 0; ni < 4; ni++) {
                    int n = wn * 32 + ni * 8 + qi * 2;
                    float v0 = (acc[mi][ni][rh*2]   - mean) * rstd;
                    float v1 = (acc[mi][ni][rh*2+1] - mean) * rstd;
                    *(__half2*)(dst + (size_t)m * HW + n) = __floats2half2_rn(v0, v1);
                }
            }
    } else if (MODE == 1) {
        __half* dst = g_mvl_h + (size_t)bb * CDIM * HW;
        const float* xb = X + (size_t)bb * CDIM * HW;
        #pragma unroll
        for (int mi = 0; mi < 4; mi++)
            #pragma unroll
            for (int rh = 0; rh < 2; rh++) {
                int m = row0 + wm * 64 + mi * 16 + quad + rh * 8;
                #pragma unroll
                for (int ni = 0; ni < 4; ni++) {
                    int n = wn * 32 + ni * 8 + qi * 2;
                    float2 xv = *(const float2*)(xb + (size_t)m * HW + n);
                    float v0 = 0.5f * xv.x + COMPC * acc[mi][ni][rh*2];
                    float v1 = 0.5f * xv.y + COMPC * acc[mi][ni][rh*2+1];
                    v0 = v0 > 0.f ? v0 : 0.f;
                    v1 = v1 > 0.f ? v1 : 0.f;
                    *(__half2*)(dst + (size_t)m * HW + n) = __floats2half2_rn(v0, v1);
                }
            }
    } else {  // MODE 3
        const float* xb = X + (size_t)bb * CDIM * HW;
        float* ob = Out + (size_t)bb * CDIM * HW;
        #pragma unroll
        for (int mi = 0; mi < 4; mi++)
            #pragma unroll
            for (int rh = 0; rh < 2; rh++) {
                int m = row0 + wm * 64 + mi * 16 + quad + rh * 8;
                #pragma unroll
                for (int ni = 0; ni < 4; ni++) {
                    int n = wn * 32 + ni * 8 + qi * 2;
                    float2 xv = *(const float2*)(xb + (size_t)m * HW + n);
                    float s0 = 1.f / (1.f + __expf(-acc[mi][ni][rh*2]));
                    float s1 = 1.f / (1.f + __expf(-acc[mi][ni][rh*2+1]));
                    float2 o;
                    o.x = xv.x + xv.x * s0;
                    o.y = xv.y + xv.y * s1;
                    *(float2*)(ob + (size_t)m * HW + n) = o;
                }
            }
    }
}

// ---------------------------------------------------------------------------
extern "C" void kernel_launch(void* const* d_in, const int* in_sizes, int n_in,
                              void* d_out, int out_size)
{
    const float* x   = (const float*)d_in[0];
    const float* pr  = (const float*)d_in[1];
    const float* wrf = (const float*)d_in[2];
    const float* wmv = (const float*)d_in[3];
    const float* wrm = (const float*)d_in[4];
    const float* wfu = (const float*)d_in[5];
    float* out = (float*)d_out;

    // One-time handle setup (2 streams + 5 events -- proven footprint).
    static cudaStream_t s1 = nullptr, s2 = nullptr;
    static cudaEvent_t  e0 = nullptr, e1 = nullptr, ed = nullptr,
                        e2 = nullptr, e3 = nullptr;
    if (s1 == nullptr) {
        cudaStreamCreateWithFlags(&s1, cudaStreamNonBlocking);
        cudaStreamCreateWithFlags(&s2, cudaStreamNonBlocking);
        cudaEventCreateWithFlags(&e0, cudaEventDisableTiming);
        cudaEventCreateWithFlags(&e1, cudaEventDisableTiming);
        cudaEventCreateWithFlags(&ed, cudaEventDisableTiming);
        cudaEventCreateWithFlags(&e2, cudaEventDisableTiming);
        cudaEventCreateWithFlags(&e3, cudaEventDisableTiming);
        cudaFuncSetAttribute(gemm0_f32b,   cudaFuncAttributeMaxDynamicSharedMemorySize, G0_SMEM);
        cudaFuncSetAttribute(gemm_hmma<1>, cudaFuncAttributeMaxDynamicSharedMemorySize, SMEM128);
        cudaFuncSetAttribute(gemm_hmma<2>, cudaFuncAttributeMaxDynamicSharedMemorySize, SMEM128);
        cudaFuncSetAttribute(gemm_hmma<3>, cudaFuncAttributeMaxDynamicSharedMemorySize, SMEM128);
    }

    __half *wrf_h, *wmv_h, *wrm_h, *wfu_h;
    float *dot_p, *pn_p;
    cudaGetSymbolAddress((void**)&wrf_h,  g_wrf_h);
    cudaGetSymbolAddress((void**)&wmv_h,  g_wmv_h);
    cudaGetSymbolAddress((void**)&wrm_h,  g_wrm_h);
    cudaGetSymbolAddress((void**)&wfu_h,  g_wfu_h);
    cudaGetSymbolAddress((void**)&dot_p,  g_dot);
    cudaGetSymbolAddress((void**)&pn_p,   g_pn);

    // ---- fork ----
    cudaEventRecord(e0, 0);
    cudaStreamWaitEvent(s1, e0, 0);
    cudaStreamWaitEvent(s2, e0, 0);

    // Branch s1: wrf conversion, then gemm0 (fp32 B) -- concurrent with dist.
    f2h_kernel<<<(RF*CDIM/4 + 255)/256, 256, 0, s1>>>(wrf, wrf_h, RF*CDIM/4);
    gemm0_f32b<<<dim3(4, PN), 256, G0_SMEM, s1>>>(wrf_h, pr);
    cudaEventRecord(e1, s1);

    // Branch s2: weight conversions
    {
        const int na4 = CDIM*TOPK*RF/4, nb4 = CDIM*CDIM/4, nc4 = CDIM*CDIM/4;
        f2h3_kernel<<<(na4 + nb4 + nc4 + 255)/256, 256, 0, s2>>>(
            wmv, wmv_h, na4, wrm, wrm_h, nb4, wfu, wfu_h, nc4);
    }

    // Main branch: zero accumulators, dist (512 blocks x 4 chunks)
    cudaMemsetAsync(dot_p, 0, NB*PN*sizeof(float), 0);
    cudaMemsetAsync(pn_p,  0, PN*sizeof(float),    0);
    dist_kernel<<<512, 256>>>(x, pr);
    cudaEventRecord(ed, 0);

    // topk on s2 (needs dist results; 1 block, warp per sample)
    cudaStreamWaitEvent(s2, ed, 0);
    topk_kernel<<<1, NB*32, 0, s2>>>();
    cudaEventRecord(e2, s2);

    // ---- join: gemm0 (s1) + topk/converts (s2) ----
    cudaStreamWaitEvent(0, e1, 0);
    cudaStreamWaitEvent(0, e2, 0);
    cudaEventRecord(e0, 0);   // reuse e0 as post-join readiness marker

    // ---- two pipelined chains of 8 samples (reuse s1; no new streams) ----
    cudaStreamWaitEvent(s1, e0, 0);
    gemm_hmma<1><<<dim3(16, NB/2), 256, SMEM128, s1>>>(wmv_h, x, nullptr, TOPK*RF, NB/2);
    gemm_hmma<2><<<dim3(16, NB/2), 256, SMEM128, s1>>>(wrm_h, nullptr, nullptr, CDIM, NB/2);
    gemm_hmma<3><<<dim3(16, NB/2), 256, SMEM128, s1>>>(wfu_h, x, out, CDIM, NB/2);
    cudaEventRecord(e3, s1);

    gemm_hmma<1><<<dim3(16, NB/2), 256, SMEM128>>>(wmv_h, x, nullptr, TOPK*RF, 0);
    gemm_hmma<2><<<dim3(16, NB/2), 256, SMEM128>>>(wrm_h, nullptr, nullptr, CDIM, 0);
    gemm_hmma<3><<<dim3(16, NB/2), 256, SMEM128>>>(wfu_h, x, out, CDIM, 0);

    cudaStreamWaitEvent(0, e3, 0);
}